// round 6
// baseline (speedup 1.0000x reference)
#include <cuda_runtime.h>
#include <cuda_bf16.h>
#include <math.h>

// Problem constants
#define TT 64
#define BB 32
#define HH 512
#define VV 32000
#define SS 64
#define MROWS (TT*BB)      // 2048
#define G4H (4*HH)         // 2048

// ---------------- scratch (static device allocations; no cudaMalloc) -------
__device__ float g_x   [MROWS*HH];     // embedded input [m,k]
__device__ float g_xw  [MROWS*G4H];    // input projection, TRANSPOSED [gate_row][m]
__device__ float g_ys0 [MROWS*HH];     // layer0 outputs [m,k]
__device__ float g_ys1 [MROWS*HH];     // layer1 outputs (dec) [m,k]
__device__ float g_h0  [2][HH*BB];     // layer0 h ping-pong, transposed [j*32+b]
__device__ float g_h1  [2][HH*BB];     // layer1 h ping-pong
__device__ float g_c0  [HH*BB];        // layer0 c, transposed
__device__ float g_c1  [HH*BB];
__device__ float g_ctx [BB*HH];        // attention context (t-invariant)
__device__ float g_base[BB*VV];        // ctx @ W2b^T
__device__ int   g_bar [2*TT];         // grid-barrier counters (zeroed per launch)

// ---------------- init: transpose initial states + zero barrier counters ----
__global__ void init_state(const float* __restrict__ hidden,
                           const float* __restrict__ cell,
                           float* __restrict__ h0, float* __restrict__ h1,
                           float* __restrict__ c0, float* __restrict__ c1,
                           int* __restrict__ bar) {
    int idx = blockIdx.x * blockDim.x + threadIdx.x;   // 0..16383
    if (idx < 2*TT) bar[idx] = 0;
    if (idx >= HH*BB) return;
    int j = idx >> 5, b = idx & 31;
    int src = b * HH + j;
    h0[idx] = hidden[src];
    h1[idx] = hidden[HH*BB + src];
    c0[idx] = cell[src];
    c1[idx] = cell[HH*BB + src];
}

// ---------------- embedding gather -----------------------------------------
__global__ void gather_emb(const int* __restrict__ tgt,
                           const float* __restrict__ emb,
                           float* __restrict__ x) {
    int m = blockIdx.x;                 // 0..2047
    int r = tgt[m];
    const float4* src = reinterpret_cast<const float4*>(emb + (size_t)r * HH);
    float4* dst = reinterpret_cast<float4*>(x + (size_t)m * HH);
    dst[threadIdx.x] = src[threadIdx.x];   // 128 threads x float4 = 512 floats
}

// ---------------- generic SGEMM: C = A[M,K] * B[N,K]^T (+bias,+rowAdd) ------
// transC=0: C[r*ldc + n] (float4 stores);  transC=1: C[n*ldc + r]
__global__ __launch_bounds__(256)
void sgemm_nt(const float* __restrict__ A, int lda,
              const float* __restrict__ B, int ldb,
              float* __restrict__ C, int ldc,
              int M, int N, int K,
              const float* __restrict__ bias0,
              const float* __restrict__ bias1,
              const float* __restrict__ rowAdd, int rowMod,
              int transC) {
    __shared__ float As[8][128];
    __shared__ float Bs[8][128];
    int tid = threadIdx.x;
    int tx = tid & 15, ty = tid >> 4;
    int bm = blockIdx.y * 128, bn = blockIdx.x * 128;
    int lr = tid >> 1;              // 0..127
    int lc = (tid & 1) * 4;         // 0 or 4
    const float* Ap = A + (size_t)(bm + lr) * lda + lc;
    const float* Bp = B + (size_t)(bn + lr) * ldb + lc;
    bool aval = (bm + lr) < M;      // N tiles are always full in our shapes
    float acc[8][8];
    #pragma unroll
    for (int i = 0; i < 8; i++)
        #pragma unroll
        for (int j = 0; j < 8; j++) acc[i][j] = 0.f;

    // register-prefetch first K-tile
    float4 a4 = aval ? *reinterpret_cast<const float4*>(Ap)
                     : make_float4(0.f,0.f,0.f,0.f);
    float4 b4 = *reinterpret_cast<const float4*>(Bp);

    for (int k0 = 0; k0 < K; k0 += 8) {
        As[lc+0][lr] = a4.x; As[lc+1][lr] = a4.y;
        As[lc+2][lr] = a4.z; As[lc+3][lr] = a4.w;
        Bs[lc+0][lr] = b4.x; Bs[lc+1][lr] = b4.y;
        Bs[lc+2][lr] = b4.z; Bs[lc+3][lr] = b4.w;
        __syncthreads();
        if (k0 + 8 < K) {   // prefetch next tile while computing this one
            a4 = aval ? *reinterpret_cast<const float4*>(Ap + k0 + 8)
                      : make_float4(0.f,0.f,0.f,0.f);
            b4 = *reinterpret_cast<const float4*>(Bp + k0 + 8);
        }
        #pragma unroll
        for (int kk = 0; kk < 8; kk++) {
            float ra[8], rb[8];
            *reinterpret_cast<float4*>(&ra[0]) = *reinterpret_cast<const float4*>(&As[kk][ty*8]);
            *reinterpret_cast<float4*>(&ra[4]) = *reinterpret_cast<const float4*>(&As[kk][ty*8+4]);
            *reinterpret_cast<float4*>(&rb[0]) = *reinterpret_cast<const float4*>(&Bs[kk][tx*8]);
            *reinterpret_cast<float4*>(&rb[4]) = *reinterpret_cast<const float4*>(&Bs[kk][tx*8+4]);
            #pragma unroll
            for (int i = 0; i < 8; i++)
                #pragma unroll
                for (int j = 0; j < 8; j++)
                    acc[i][j] = fmaf(ra[i], rb[j], acc[i][j]);
        }
        __syncthreads();
    }
    #pragma unroll
    for (int i = 0; i < 8; i++) {
        int r = bm + ty*8 + i;
        if (r >= M) continue;
        if (!transC) {
            #pragma unroll
            for (int j0 = 0; j0 < 8; j0 += 4) {
                int cidx = bn + tx*8 + j0;
                float4 v = make_float4(acc[i][j0], acc[i][j0+1], acc[i][j0+2], acc[i][j0+3]);
                if (bias0) {
                    float4 t = *reinterpret_cast<const float4*>(bias0 + cidx);
                    v.x += t.x; v.y += t.y; v.z += t.z; v.w += t.w;
                }
                if (bias1) {
                    float4 t = *reinterpret_cast<const float4*>(bias1 + cidx);
                    v.x += t.x; v.y += t.y; v.z += t.z; v.w += t.w;
                }
                if (rowAdd) {
                    float4 t = *reinterpret_cast<const float4*>(
                        rowAdd + (size_t)(r % rowMod) * ldc + cidx);
                    v.x += t.x; v.y += t.y; v.z += t.z; v.w += t.w;
                }
                *reinterpret_cast<float4*>(C + (size_t)r * ldc + cidx) = v;
            }
        } else {
            #pragma unroll
            for (int j = 0; j < 8; j++) {
                int cidx = bn + tx*8 + j;
                float v = acc[i][j];
                if (bias0) v += bias0[cidx];
                if (bias1) v += bias1[cidx];
                C[(size_t)cidx * ldc + r] = v;
            }
        }
    }
}

// ---------------- persistent LSTM layer -------------------------------------
// grid = 128 CTAs x 128 threads; all CTAs co-resident (128 < 148 SMs).
// CTA c owns h-columns j in {4c..4c+3}. Warp w -> j_local, lane -> b.
// W slice (16 gate-rows x 512) lives in smem for the whole layer.
// h exchanged via global ping-pong + per-step arrive counters.
__device__ __forceinline__ float sigmoidf_(float x) {
    return 1.f / (1.f + expf(-x));
}

__global__ __launch_bounds__(128)
void lstm_persist(const float* __restrict__ xwT,   // [2048][2048] gate_row-major
                  const float* __restrict__ W_hh,  // [2048][512]
                  float* __restrict__ hbuf,        // [2][512*32] transposed
                  float* __restrict__ cbuf,        // [512*32]    transposed
                  float* __restrict__ ys,          // [2048][512]
                  int* __restrict__ bar)           // [TT] zeroed counters
{
    extern __shared__ float smem[];
    float* Ws = smem;            // [4 gates][4 j_local][512]  = 8192 floats
    float* Hs = smem + 4*4*HH;   // [512][32]                  = 16384 floats

    int tid = threadIdx.x;
    int w   = tid >> 5;          // j_local
    int b   = tid & 31;
    int cta = blockIdx.x;
    int jg  = cta * 4 + w;       // global h-column 0..511

    // Load this CTA's 16 gate-rows of W_hh into smem (once per layer).
    #pragma unroll
    for (int r = 0; r < 16; r++) {
        int g = r >> 2, jl = r & 3;
        const float4* src = reinterpret_cast<const float4*>(
            W_hh + (size_t)(g*HH + cta*4 + jl) * HH);
        float4* dst = reinterpret_cast<float4*>(&Ws[(g*4 + jl) * HH]);
        dst[tid] = src[tid];     // 128 float4 per row, one per thread
    }
    float creg = cbuf[jg*32 + b];
    __syncthreads();

    const float4* wi = reinterpret_cast<const float4*>(&Ws[(0*4 + w) * HH]);
    const float4* wf = reinterpret_cast<const float4*>(&Ws[(1*4 + w) * HH]);
    const float4* wg = reinterpret_cast<const float4*>(&Ws[(2*4 + w) * HH]);
    const float4* wo = reinterpret_cast<const float4*>(&Ws[(3*4 + w) * HH]);

    volatile int* vbar = (volatile int*)bar;

    for (int t = 0; t < TT; t++) {
        // stage h(t) into smem (L2-coherent loads; L1 may hold stale lines)
        {
            const float4* hsrc = reinterpret_cast<const float4*>(hbuf + (t & 1) * HH*BB);
            float4* hdst = reinterpret_cast<float4*>(Hs);
            #pragma unroll
            for (int i = 0; i < 32; i++)
                hdst[tid + (i << 7)] = __ldcg(hsrc + tid + (i << 7));
        }
        __syncthreads();

        int m = t*32 + b;
        float ai = xwT[(size_t)(0*HH + jg) * MROWS + m];
        float af = xwT[(size_t)(1*HH + jg) * MROWS + m];
        float ag = xwT[(size_t)(2*HH + jg) * MROWS + m];
        float ao = xwT[(size_t)(3*HH + jg) * MROWS + m];

        #pragma unroll 8
        for (int k4 = 0; k4 < HH/4; ++k4) {
            float4 vi = wi[k4], vf = wf[k4], vg = wg[k4], vo = wo[k4];
            int k = k4 << 2;
            float h0 = Hs[(k+0)*32 + b];
            float h1 = Hs[(k+1)*32 + b];
            float h2 = Hs[(k+2)*32 + b];
            float h3 = Hs[(k+3)*32 + b];
            ai = fmaf(vi.x, h0, ai); af = fmaf(vf.x, h0, af);
            ag = fmaf(vg.x, h0, ag); ao = fmaf(vo.x, h0, ao);
            ai = fmaf(vi.y, h1, ai); af = fmaf(vf.y, h1, af);
            ag = fmaf(vg.y, h1, ag); ao = fmaf(vo.y, h1, ao);
            ai = fmaf(vi.z, h2, ai); af = fmaf(vf.z, h2, af);
            ag = fmaf(vg.z, h2, ag); ao = fmaf(vo.z, h2, ao);
            ai = fmaf(vi.w, h3, ai); af = fmaf(vf.w, h3, af);
            ag = fmaf(vg.w, h3, ag); ao = fmaf(vo.w, h3, ao);
        }

        float ig = sigmoidf_(ai);
        float fg = sigmoidf_(af);
        float gg = tanhf(ag);
        float og = sigmoidf_(ao);
        float c_new = fmaf(fg, creg, ig * gg);
        float h_new = og * tanhf(c_new);
        creg = c_new;

        hbuf[((t+1) & 1) * HH*BB + jg*32 + b] = h_new;
        ys[(size_t)m * HH + jg] = h_new;
        if (t == TT-1) cbuf[jg*32 + b] = creg;

        // grid barrier: release writes, arrive, wait for all 128 CTAs
        __threadfence();
        __syncthreads();
        if (tid == 0) {
            atomicAdd(&bar[t], 1);
            while (vbar[t] < (int)gridDim.x) { __nanosleep(32); }
            __threadfence();
        }
        __syncthreads();
    }
}

// ---------------- context: masked mean over S (exact softmax shortcut) ------
// scores[t,s,b,h] = NEG where mask, else att[t,b,h] (same value for every
// unmasked s) -> softmax over s is exactly uniform over unmasked positions
// (exp(NEG - att) underflows to 0.0f). Hence ctx = masked mean of enc_output,
// independent of t and of W1 entirely.
__global__ void ctx_kernel(const float* __restrict__ enc,
                           const int* __restrict__ src_mask,
                           float* __restrict__ ctx) {
    int b = blockIdx.x;       // 0..31
    int h = threadIdx.x;      // 0..511
    float s_un = 0.f, s_all = 0.f;
    int cnt = 0;
    #pragma unroll 4
    for (int s = 0; s < SS; s++) {
        float v = enc[((size_t)s * BB + b) * HH + h];
        int mk = src_mask[s * BB + b];
        s_all += v;
        if (mk == 0) { s_un += v; cnt++; }
    }
    ctx[b * HH + h] = (cnt > 0) ? (s_un * (1.f / (float)cnt))
                                : (s_all * (1.f / (float)SS));
}

// ---------------- tail: write hs, cs after the logits ------------------------
__global__ void tail_kernel(const float* __restrict__ ys0,
                            const float* __restrict__ ys1,
                            const float* __restrict__ c0,
                            const float* __restrict__ c1,
                            float* __restrict__ out) {
    int idx = blockIdx.x * blockDim.x + threadIdx.x;  // 0..65535
    if (idx >= 4*HH*BB) return;
    int seg = idx >> 14;          // 0:h_l0 1:h_l1 2:c_l0 3:c_l1
    int i   = idx & 16383;
    int b = i >> 9, j = i & 511;
    float v;
    if      (seg == 0) v = ys0[((size_t)(TT-1)*BB + b) * HH + j];
    else if (seg == 1) v = ys1[((size_t)(TT-1)*BB + b) * HH + j];
    else if (seg == 2) v = c0[j*32 + b];
    else               v = c1[j*32 + b];
    out[(size_t)MROWS * VV + idx] = v;
}

// ---------------- launch -----------------------------------------------------
extern "C" void kernel_launch(void* const* d_in, const int* in_sizes, int n_in,
                              void* d_out, int out_size) {
    (void)in_sizes; (void)n_in; (void)out_size;
    const int*   tgt     = (const int*)  d_in[0];
    const float* hidden  = (const float*)d_in[1];
    const float* cell    = (const float*)d_in[2];
    const float* enc     = (const float*)d_in[3];
    const int*   srcmask = (const int*)  d_in[4];
    const float* emb     = (const float*)d_in[5];
    const float* Wih0    = (const float*)d_in[6];
    const float* Whh0    = (const float*)d_in[7];
    const float* bih0    = (const float*)d_in[8];
    const float* bhh0    = (const float*)d_in[9];
    const float* Wih1    = (const float*)d_in[10];
    const float* Whh1    = (const float*)d_in[11];
    const float* bih1    = (const float*)d_in[12];
    const float* bhh1    = (const float*)d_in[13];
    // d_in[14] = W1 : provably irrelevant to output (softmax shortcut)
    const float* W2      = (const float*)d_in[15];
    float* out = (float*)d_out;

    float *p_x, *p_xw, *p_ys0, *p_ys1, *p_h0, *p_h1, *p_c0, *p_c1, *p_ctx, *p_base;
    int *p_bar;
    cudaGetSymbolAddress((void**)&p_x,    g_x);
    cudaGetSymbolAddress((void**)&p_xw,   g_xw);
    cudaGetSymbolAddress((void**)&p_ys0,  g_ys0);
    cudaGetSymbolAddress((void**)&p_ys1,  g_ys1);
    cudaGetSymbolAddress((void**)&p_h0,   g_h0);
    cudaGetSymbolAddress((void**)&p_h1,   g_h1);
    cudaGetSymbolAddress((void**)&p_c0,   g_c0);
    cudaGetSymbolAddress((void**)&p_c1,   g_c1);
    cudaGetSymbolAddress((void**)&p_ctx,  g_ctx);
    cudaGetSymbolAddress((void**)&p_base, g_base);
    cudaGetSymbolAddress((void**)&p_bar,  g_bar);

    // no static guard (harness rule) — idempotent, cheap, capture-legal
    const int PERSIST_SMEM = (4*4*HH + HH*BB) * sizeof(float);  // 96 KB
    cudaFuncSetAttribute(lstm_persist,
                         cudaFuncAttributeMaxDynamicSharedMemorySize,
                         PERSIST_SMEM);

    // 1. init recurrent state (transposed ping-pong buffers) + zero barriers
    init_state<<<64, 256>>>(hidden, cell, p_h0, p_h1, p_c0, p_c1, p_bar);

    // 2. embedding gather
    gather_emb<<<MROWS, 128>>>(tgt, emb, p_x);

    // 3. input projection layer0 (transposed store): xwT = (x @ Wih0^T + b)^T
    sgemm_nt<<<dim3(G4H/128, MROWS/128), 256>>>(p_x, HH, Wih0, HH, p_xw, MROWS,
                                                MROWS, G4H, HH, bih0, bhh0,
                                                nullptr, 1, 1);

    // 4. layer0 recurrence (persistent, weights in smem)
    lstm_persist<<<128, 128, PERSIST_SMEM>>>(p_xw, Whh0, p_h0, p_c0, p_ys0, p_bar);

    // 5. input projection layer1 (transposed store)
    sgemm_nt<<<dim3(G4H/128, MROWS/128), 256>>>(p_ys0, HH, Wih1, HH, p_xw, MROWS,
                                                MROWS, G4H, HH, bih1, bhh1,
                                                nullptr, 1, 1);

    // 6. layer1 recurrence
    lstm_persist<<<128, 128, PERSIST_SMEM>>>(p_xw, Whh1, p_h1, p_c1, p_ys1, p_bar + TT);

    // 7. attention context (t-invariant masked mean)
    ctx_kernel<<<BB, HH>>>(enc, srcmask, p_ctx);

    // 8. base = ctx @ W2[:,512:]^T  -> [32, 32000]
    sgemm_nt<<<dim3(VV/128, 1), 256>>>(p_ctx, HH, W2 + HH, 2*HH, p_base, VV,
                                       BB, VV, HH, nullptr, nullptr, nullptr, 1, 0);

    // 9. out = dec @ W2[:,:512]^T + base[b]  -> [2048, 32000]
    sgemm_nt<<<dim3(VV/128, MROWS/128), 256>>>(p_ys1, HH, W2, 2*HH, out, VV,
                                               MROWS, VV, HH, nullptr, nullptr,
                                               p_base, BB, 0);

    // 10. hs / cs tail
    tail_kernel<<<64, 1024>>>(p_ys0, p_ys1, p_c0, p_c1, out);
}

// round 9
// speedup vs baseline: 1.3402x; 1.3402x over previous
#include <cuda_runtime.h>
#include <cuda_bf16.h>
#include <math.h>
#include <stdint.h>

#define TT 64
#define BB 32
#define HH 512
#define VV 32000
#define SS 64
#define MROWS (TT*BB)      // 2048
#define G4H (4*HH)         // 2048
#define KTOT 1024

// ---- static scratch ----
__device__ float g_x   [MROWS*HH];
__device__ float g_xw  [MROWS*G4H];          // input proj, transposed [gate_row][m]
__device__ float g_ys0 [MROWS*HH];
__device__ float g_ys1 [MROWS*HH];
__device__ float g_h0  [2][HH*BB];
__device__ float g_h1  [2][HH*BB];
__device__ float g_c0  [HH*BB];
__device__ float g_c1  [HH*BB];
__device__ float g_ctx [BB*HH];
__device__ int   g_bar [2*TT];
__device__ __nv_bfloat16 g_Ah[MROWS*KTOT];
__device__ __nv_bfloat16 g_Al[MROWS*KTOT];
__device__ __nv_bfloat16 g_Wh[(size_t)VV*KTOT];
__device__ __nv_bfloat16 g_Wl[(size_t)VV*KTOT];

extern __shared__ char dynsmem[];

#define SWZ(o) ((o) ^ (((o) >> 3) & 0x70))

__device__ __forceinline__ uint32_t s2u(const void* p) {
    uint32_t a;
    asm("{ .reg .u64 t; cvta.to.shared.u64 t, %1; cvt.u32.u64 %0, t; }" : "=r"(a) : "l"(p));
    return a;
}
__device__ __forceinline__ void cp16(uint32_t smem, const void* g) {
    asm volatile("cp.async.cg.shared.global [%0], [%1], 16;" :: "r"(smem), "l"(g));
}
#define CP_COMMIT() asm volatile("cp.async.commit_group;" ::: "memory")
#define CP_WAIT1()  asm volatile("cp.async.wait_group 1;" ::: "memory")
#define CP_WAIT0()  asm volatile("cp.async.wait_group 0;" ::: "memory")

__device__ __forceinline__ void ldsm4(uint32_t* r, uint32_t addr) {
    asm volatile("ldmatrix.sync.aligned.m8n8.x4.shared.b16 {%0,%1,%2,%3}, [%4];"
        : "=r"(r[0]), "=r"(r[1]), "=r"(r[2]), "=r"(r[3]) : "r"(addr));
}
__device__ __forceinline__ void mma16816(float* d, const uint32_t* a, const uint32_t* b) {
    asm volatile(
        "mma.sync.aligned.m16n8k16.row.col.f32.bf16.bf16.f32 "
        "{%0,%1,%2,%3}, {%4,%5,%6,%7}, {%8,%9}, {%0,%1,%2,%3};"
        : "+f"(d[0]), "+f"(d[1]), "+f"(d[2]), "+f"(d[3])
        : "r"(a[0]), "r"(a[1]), "r"(a[2]), "r"(a[3]), "r"(b[0]), "r"(b[1]));
}

// ---- init / gather ----
__global__ void init_state(const float* __restrict__ hidden, const float* __restrict__ cell,
                           float* h0, float* h1, float* c0, float* c1, int* bar) {
    int idx = blockIdx.x * blockDim.x + threadIdx.x;
    if (idx < 2*TT) bar[idx] = 0;
    if (idx >= HH*BB) return;
    int j = idx >> 5, b = idx & 31;
    int src = b * HH + j;
    h0[idx] = hidden[src];  h1[idx] = hidden[HH*BB + src];
    c0[idx] = cell[src];    c1[idx] = cell[HH*BB + src];
}
__global__ void gather_emb(const int* __restrict__ tgt, const float* __restrict__ emb,
                           float* __restrict__ x) {
    int m = blockIdx.x, r = tgt[m];
    reinterpret_cast<float4*>(x + (size_t)m * HH)[threadIdx.x] =
        reinterpret_cast<const float4*>(emb + (size_t)r * HH)[threadIdx.x];
}

// ---- SGEMM for input projections, transposed store C[n][m] ----
__global__ __launch_bounds__(256)
void sgemm_nt_t(const float* __restrict__ A, const float* __restrict__ B,
                float* __restrict__ C,
                const float* __restrict__ bias0, const float* __restrict__ bias1) {
    __shared__ float As[8][128], Bs[8][128];
    int tid = threadIdx.x, tx = tid & 15, ty = tid >> 4;
    int bm = blockIdx.y * 128, bn = blockIdx.x * 128;
    int lr = tid >> 1, lc = (tid & 1) * 4;
    const float* Ap = A + (size_t)(bm + lr) * HH + lc;
    const float* Bp = B + (size_t)(bn + lr) * HH + lc;
    float acc[8][8];
    #pragma unroll
    for (int i = 0; i < 8; i++)
        #pragma unroll
        for (int j = 0; j < 8; j++) acc[i][j] = 0.f;
    float4 a4 = *reinterpret_cast<const float4*>(Ap);
    float4 b4 = *reinterpret_cast<const float4*>(Bp);
    for (int k0 = 0; k0 < HH; k0 += 8) {
        As[lc+0][lr]=a4.x; As[lc+1][lr]=a4.y; As[lc+2][lr]=a4.z; As[lc+3][lr]=a4.w;
        Bs[lc+0][lr]=b4.x; Bs[lc+1][lr]=b4.y; Bs[lc+2][lr]=b4.z; Bs[lc+3][lr]=b4.w;
        __syncthreads();
        if (k0 + 8 < HH) {
            a4 = *reinterpret_cast<const float4*>(Ap + k0 + 8);
            b4 = *reinterpret_cast<const float4*>(Bp + k0 + 8);
        }
        #pragma unroll
        for (int kk = 0; kk < 8; kk++) {
            float ra[8], rb[8];
            *reinterpret_cast<float4*>(&ra[0]) = *reinterpret_cast<const float4*>(&As[kk][ty*8]);
            *reinterpret_cast<float4*>(&ra[4]) = *reinterpret_cast<const float4*>(&As[kk][ty*8+4]);
            *reinterpret_cast<float4*>(&rb[0]) = *reinterpret_cast<const float4*>(&Bs[kk][tx*8]);
            *reinterpret_cast<float4*>(&rb[4]) = *reinterpret_cast<const float4*>(&Bs[kk][tx*8+4]);
            #pragma unroll
            for (int i = 0; i < 8; i++)
                #pragma unroll
                for (int j = 0; j < 8; j++) acc[i][j] = fmaf(ra[i], rb[j], acc[i][j]);
        }
        __syncthreads();
    }
    #pragma unroll
    for (int i = 0; i < 8; i++) {
        int r = bm + ty*8 + i;
        #pragma unroll
        for (int j = 0; j < 8; j++) {
            int n = bn + tx*8 + j;
            C[(size_t)n * MROWS + r] = acc[i][j] + bias0[n] + bias1[n];
        }
    }
}

// ---- persistent LSTM (known-good) ----
__device__ __forceinline__ float sigmoidf_(float x) { return 1.f / (1.f + expf(-x)); }

__global__ __launch_bounds__(128)
void lstm_persist(const float* __restrict__ xwT, const float* __restrict__ W_hh,
                  float* __restrict__ hbuf, float* __restrict__ cbuf,
                  float* __restrict__ ys, int* __restrict__ bar) {
    float* smemf = reinterpret_cast<float*>(dynsmem);
    float* Ws = smemf;
    float* Hs = smemf + 4*4*HH;
    int tid = threadIdx.x, w = tid >> 5, b = tid & 31, cta = blockIdx.x;
    int jg = cta * 4 + w;
    #pragma unroll
    for (int r = 0; r < 16; r++) {
        int g = r >> 2, jl = r & 3;
        reinterpret_cast<float4*>(&Ws[(g*4 + jl) * HH])[tid] =
            reinterpret_cast<const float4*>(W_hh + (size_t)(g*HH + cta*4 + jl) * HH)[tid];
    }
    float creg = cbuf[jg*32 + b];
    __syncthreads();
    const float4* wi = reinterpret_cast<const float4*>(&Ws[(0*4 + w) * HH]);
    const float4* wf = reinterpret_cast<const float4*>(&Ws[(1*4 + w) * HH]);
    const float4* wg = reinterpret_cast<const float4*>(&Ws[(2*4 + w) * HH]);
    const float4* wo = reinterpret_cast<const float4*>(&Ws[(3*4 + w) * HH]);
    volatile int* vbar = (volatile int*)bar;
    for (int t = 0; t < TT; t++) {
        const float4* hsrc = reinterpret_cast<const float4*>(hbuf + (t & 1) * HH*BB);
        float4* hdst = reinterpret_cast<float4*>(Hs);
        #pragma unroll
        for (int i = 0; i < 32; i++) hdst[tid + (i << 7)] = __ldcg(hsrc + tid + (i << 7));
        __syncthreads();
        int m = t*32 + b;
        float ai = xwT[(size_t)(0*HH + jg) * MROWS + m];
        float af = xwT[(size_t)(1*HH + jg) * MROWS + m];
        float ag = xwT[(size_t)(2*HH + jg) * MROWS + m];
        float ao = xwT[(size_t)(3*HH + jg) * MROWS + m];
        #pragma unroll 8
        for (int k4 = 0; k4 < HH/4; ++k4) {
            float4 vi = wi[k4], vf = wf[k4], vg = wg[k4], vo = wo[k4];
            int k = k4 << 2;
            float h0 = Hs[(k+0)*32 + b], h1 = Hs[(k+1)*32 + b];
            float h2 = Hs[(k+2)*32 + b], h3 = Hs[(k+3)*32 + b];
            ai = fmaf(vi.x,h0,ai); af = fmaf(vf.x,h0,af); ag = fmaf(vg.x,h0,ag); ao = fmaf(vo.x,h0,ao);
            ai = fmaf(vi.y,h1,ai); af = fmaf(vf.y,h1,af); ag = fmaf(vg.y,h1,ag); ao = fmaf(vo.y,h1,ao);
            ai = fmaf(vi.z,h2,ai); af = fmaf(vf.z,h2,af); ag = fmaf(vg.z,h2,ag); ao = fmaf(vo.z,h2,ao);
            ai = fmaf(vi.w,h3,ai); af = fmaf(vf.w,h3,af); ag = fmaf(vg.w,h3,ag); ao = fmaf(vo.w,h3,ao);
        }
        float ig = sigmoidf_(ai), fg = sigmoidf_(af);
        float gg = tanhf(ag),    og = sigmoidf_(ao);
        float c_new = fmaf(fg, creg, ig * gg);
        float h_new = og * tanhf(c_new);
        creg = c_new;
        hbuf[((t+1)&1) * HH*BB + jg*32 + b] = h_new;
        ys[(size_t)m * HH + jg] = h_new;
        if (t == TT-1) cbuf[jg*32 + b] = creg;
        __threadfence();
        __syncthreads();
        if (tid == 0) {
            atomicAdd(&bar[t], 1);
            while (vbar[t] < (int)gridDim.x) { __nanosleep(32); }
            __threadfence();
        }
        __syncthreads();
    }
}

// ---- ctx: exact softmax shortcut = masked mean over S ----
__global__ void ctx_kernel(const float* __restrict__ enc, const int* __restrict__ src_mask,
                           float* __restrict__ ctx) {
    int b = blockIdx.x, h = threadIdx.x;
    float s_un = 0.f, s_all = 0.f; int cnt = 0;
    #pragma unroll 4
    for (int s = 0; s < SS; s++) {
        float v = enc[((size_t)s * BB + b) * HH + h];
        s_all += v;
        if (src_mask[s * BB + b] == 0) { s_un += v; cnt++; }
    }
    ctx[b * HH + h] = (cnt > 0) ? (s_un / (float)cnt) : (s_all / (float)SS);
}

// ---- fp32 -> bf16 hi/lo split converters ----
__device__ __forceinline__ void split8(const float* src, __nv_bfloat16* hi, __nv_bfloat16* lo) {
    float4 f0 = *reinterpret_cast<const float4*>(src);
    float4 f1 = *reinterpret_cast<const float4*>(src + 4);
    float fv[8] = {f0.x,f0.y,f0.z,f0.w,f1.x,f1.y,f1.z,f1.w};
    __nv_bfloat16 h8[8], l8[8];
    #pragma unroll
    for (int q = 0; q < 8; q++) {
        h8[q] = __float2bfloat16_rn(fv[q]);
        l8[q] = __float2bfloat16_rn(fv[q] - __bfloat162float(h8[q]));
    }
    *reinterpret_cast<uint4*>(hi) = *reinterpret_cast<uint4*>(h8);
    *reinterpret_cast<uint4*>(lo) = *reinterpret_cast<uint4*>(l8);
}
__global__ void conv_w(const float* __restrict__ W2, __nv_bfloat16* hi, __nv_bfloat16* lo) {
    size_t i = ((size_t)blockIdx.x * blockDim.x + threadIdx.x) * 8;
    split8(W2 + i, hi + i, lo + i);
}
__global__ void conv_a(const float* __restrict__ dec, const float* __restrict__ ctx,
                       __nv_bfloat16* hi, __nv_bfloat16* lo) {
    int m = blockIdx.x, t8 = threadIdx.x * 8;
    const float* src = (t8 < HH) ? dec + (size_t)m*HH + t8
                                 : ctx + (size_t)(m & 31)*HH + (t8 - HH);
    size_t o = (size_t)m * KTOT + t8;
    split8(src, hi + o, lo + o);
}

// ---- mma.sync logits GEMM: out[2048,32000] = Acat @ W2cat^T ----
// 3-pass bf16 split: D = Ah@Bh + Ah@Bl + Al@Bh (fp32 mma accum).
// CTA 128x128, 8 warps (warp tile 32x64), K-chunks of 64, cp.async double buffer.
#define CHUNKS 16
#define PLANE 16384                      // 128 rows x 128B (one 64-col bf16 plane)
#define BUFSTR (4*PLANE)                 // Ah,Al,Bh,Bl = 64 KB
#define GSMEM  (2*BUFSTR)                // 128 KB

__global__ __launch_bounds__(256, 1)
void gemm_logits_mma(const __nv_bfloat16* __restrict__ Ah, const __nv_bfloat16* __restrict__ Al,
                     const __nv_bfloat16* __restrict__ Bh, const __nv_bfloat16* __restrict__ Bl,
                     float* __restrict__ out) {
    uint32_t sb = s2u(dynsmem);
    int tid = threadIdx.x, wid = tid >> 5, lane = tid & 31;
    int bm = blockIdx.x * 128, bn = blockIdx.y * 128;
    int wm = (wid & 3) * 32;     // warp row base within tile
    int wn = (wid >> 2) * 64;    // warp col base within tile

    float acc[2][8][4];
    #pragma unroll
    for (int mt = 0; mt < 2; mt++)
        #pragma unroll
        for (int nt = 0; nt < 8; nt++)
            #pragma unroll
            for (int q = 0; q < 4; q++) acc[mt][nt][q] = 0.f;

    const __nv_bfloat16* gsrc[4] = {Ah, Al, Bh, Bl};

    // fill: 4096 x 16B items; plane p, item j: r=j>>3, seg=j&7
    auto fill = [&](int c, int buf) {
        uint32_t base = sb + buf * BUFSTR;
        #pragma unroll
        for (int it = 0; it < 16; it++) {
            int i = tid + it * 256;
            int p = i >> 10, j = i & 1023;
            int r = j >> 3, seg = j & 7;
            int grow = (p < 2) ? (bm + r) : (bn + r);
            const __nv_bfloat16* g = gsrc[p] + ((size_t)grow << 10) + (c << 6) + (seg << 3);
            cp16(base + p * PLANE + SWZ((uint32_t)(r * 128 + seg * 16)), g);
        }
        CP_COMMIT();
    };

    fill(0, 0);
    for (int c = 0; c < CHUNKS; c++) {
        int buf = c & 1;
        if (c + 1 < CHUNKS) { fill(c + 1, buf ^ 1); CP_WAIT1(); }
        else                { CP_WAIT0(); }
        __syncthreads();

        uint32_t base = sb + buf * BUFSTR;
        #pragma unroll
        for (int kk = 0; kk < 4; kk++) {
            // A fragments: hi and lo, 2 m-tiles each
            uint32_t afh[2][4], afl[2][4];
            #pragma unroll
            for (int mt = 0; mt < 2; mt++) {
                int r = wm + mt * 16 + (lane & 15);
                uint32_t off = SWZ((uint32_t)(r * 128 + kk * 32 + (lane >> 4) * 16));
                ldsm4(afh[mt], base + 0 * PLANE + off);
                ldsm4(afl[mt], base + 1 * PLANE + off);
            }
            // B fragments: hi and lo, 4 n-tile-pairs each (each x4 = two n8 tiles)
            uint32_t bfh[4][4], bfl[4][4];
            #pragma unroll
            for (int np = 0; np < 4; np++) {
                int nrow = wn + np * 16 + (lane & 7) + ((lane >> 4) << 3);
                uint32_t off = SWZ((uint32_t)(nrow * 128 + kk * 32 + ((lane >> 3) & 1) * 16));
                ldsm4(bfh[np], base + 2 * PLANE + off);
                ldsm4(bfl[np], base + 3 * PLANE + off);
            }
            #pragma unroll
            for (int mt = 0; mt < 2; mt++)
                #pragma unroll
                for (int nt = 0; nt < 8; nt++) {
                    const uint32_t* bh = &bfh[nt >> 1][(nt & 1) * 2];
                    const uint32_t* bl = &bfl[nt >> 1][(nt & 1) * 2];
                    mma16816(acc[mt][nt], afh[mt], bh);   // hh
                    mma16816(acc[mt][nt], afh[mt], bl);   // hl
                    mma16816(acc[mt][nt], afl[mt], bh);   // lh
                }
        }
        __syncthreads();
    }

    // epilogue: d0,d1 -> row+0, d2,d3 -> row+8; cols (lane&3)*2
    #pragma unroll
    for (int mt = 0; mt < 2; mt++) {
        int r0 = bm + wm + mt * 16 + (lane >> 2);
        #pragma unroll
        for (int nt = 0; nt < 8; nt++) {
            int cidx = bn + wn + nt * 8 + (lane & 3) * 2;
            *reinterpret_cast<float2*>(out + (size_t)r0 * VV + cidx) =
                make_float2(acc[mt][nt][0], acc[mt][nt][1]);
            *reinterpret_cast<float2*>(out + (size_t)(r0 + 8) * VV + cidx) =
                make_float2(acc[mt][nt][2], acc[mt][nt][3]);
        }
    }
}

// ---- tail: hs / cs ----
__global__ void tail_kernel(const float* __restrict__ ys0, const float* __restrict__ ys1,
                            const float* __restrict__ c0, const float* __restrict__ c1,
                            float* __restrict__ out) {
    int idx = blockIdx.x * blockDim.x + threadIdx.x;
    if (idx >= 4*HH*BB) return;
    int seg = idx >> 14, i = idx & 16383;
    int b = i >> 9, j = i & 511;
    float v;
    if      (seg == 0) v = ys0[((size_t)(TT-1)*BB + b) * HH + j];
    else if (seg == 1) v = ys1[((size_t)(TT-1)*BB + b) * HH + j];
    else if (seg == 2) v = c0[j*32 + b];
    else               v = c1[j*32 + b];
    out[(size_t)MROWS * VV + idx] = v;
}

// ---- launch ----
extern "C" void kernel_launch(void* const* d_in, const int* in_sizes, int n_in,
                              void* d_out, int out_size) {
    (void)in_sizes; (void)n_in; (void)out_size;
    const int*   tgt     = (const int*)  d_in[0];
    const float* hidden  = (const float*)d_in[1];
    const float* cell    = (const float*)d_in[2];
    const float* enc     = (const float*)d_in[3];
    const int*   srcmask = (const int*)  d_in[4];
    const float* emb     = (const float*)d_in[5];
    const float* Wih0    = (const float*)d_in[6];
    const float* Whh0    = (const float*)d_in[7];
    const float* bih0    = (const float*)d_in[8];
    const float* bhh0    = (const float*)d_in[9];
    const float* Wih1    = (const float*)d_in[10];
    const float* Whh1    = (const float*)d_in[11];
    const float* bih1    = (const float*)d_in[12];
    const float* bhh1    = (const float*)d_in[13];
    // d_in[14] = W1: provably irrelevant (softmax shortcut)
    const float* W2      = (const float*)d_in[15];
    float* out = (float*)d_out;

    float *p_x, *p_xw, *p_ys0, *p_ys1, *p_h0, *p_h1, *p_c0, *p_c1, *p_ctx;
    __nv_bfloat16 *p_Ah, *p_Al, *p_Wh, *p_Wl;
    int *p_bar;
    cudaGetSymbolAddress((void**)&p_x,   g_x);
    cudaGetSymbolAddress((void**)&p_xw,  g_xw);
    cudaGetSymbolAddress((void**)&p_ys0, g_ys0);
    cudaGetSymbolAddress((void**)&p_ys1, g_ys1);
    cudaGetSymbolAddress((void**)&p_h0,  g_h0);
    cudaGetSymbolAddress((void**)&p_h1,  g_h1);
    cudaGetSymbolAddress((void**)&p_c0,  g_c0);
    cudaGetSymbolAddress((void**)&p_c1,  g_c1);
    cudaGetSymbolAddress((void**)&p_ctx, g_ctx);
    cudaGetSymbolAddress((void**)&p_Ah,  g_Ah);
    cudaGetSymbolAddress((void**)&p_Al,  g_Al);
    cudaGetSymbolAddress((void**)&p_Wh,  g_Wh);
    cudaGetSymbolAddress((void**)&p_Wl,  g_Wl);
    cudaGetSymbolAddress((void**)&p_bar, g_bar);

    const int PERSIST_SMEM = (4*4*HH + HH*BB) * sizeof(float);  // 96 KB
    cudaFuncSetAttribute(lstm_persist, cudaFuncAttributeMaxDynamicSharedMemorySize, PERSIST_SMEM);
    cudaFuncSetAttribute(gemm_logits_mma, cudaFuncAttributeMaxDynamicSharedMemorySize, GSMEM);

    init_state<<<64, 256>>>(hidden, cell, p_h0, p_h1, p_c0, p_c1, p_bar);
    gather_emb<<<MROWS, 128>>>(tgt, emb, p_x);
    conv_w<<<(int)(((size_t)VV*KTOT)/8/256), 256>>>(W2, p_Wh, p_Wl);

    sgemm_nt_t<<<dim3(G4H/128, MROWS/128), 256>>>(p_x, Wih0, p_xw, bih0, bhh0);
    lstm_persist<<<128, 128, PERSIST_SMEM>>>(p_xw, Whh0, p_h0, p_c0, p_ys0, p_bar);
    sgemm_nt_t<<<dim3(G4H/128, MROWS/128), 256>>>(p_ys0, Wih1, p_xw, bih1, bhh1);
    lstm_persist<<<128, 128, PERSIST_SMEM>>>(p_xw, Whh1, p_h1, p_c1, p_ys1, p_bar + TT);

    ctx_kernel<<<BB, HH>>>(enc, srcmask, p_ctx);
    conv_a<<<MROWS, 128>>>(p_ys1, p_ctx, p_Ah, p_Al);

    gemm_logits_mma<<<dim3(MROWS/128, VV/128), 256, GSMEM>>>(p_Ah, p_Al, p_Wh, p_Wl, out);

    tail_kernel<<<64, 1024>>>(p_ys0, p_ys1, p_c0, p_c1, out);
}

// round 11
// speedup vs baseline: 1.5739x; 1.1744x over previous
#include <cuda_runtime.h>
#include <cuda_bf16.h>
#include <math.h>
#include <stdint.h>

#define TT 64
#define BB 32
#define HH 512
#define VV 32000
#define SS 64
#define MROWS (TT*BB)      // 2048
#define G4H (4*HH)         // 2048
#define KTOT 1024

// ---- static scratch ----
__device__ float g_x   [MROWS*HH];
__device__ float g_xw  [MROWS*G4H];          // input proj, transposed [gate_row][m]
__device__ float g_ys0 [MROWS*HH];
__device__ float g_ys1 [MROWS*HH];
__device__ float g_h0  [2][HH*BB];
__device__ float g_h1  [2][HH*BB];
__device__ float g_c0  [HH*BB];
__device__ float g_c1  [HH*BB];
__device__ float g_ctx [BB*HH];
__device__ int   g_bar [2*TT];
__device__ __nv_bfloat16 g_Ah[MROWS*KTOT];
__device__ __nv_bfloat16 g_Al[MROWS*KTOT];
__device__ __nv_bfloat16 g_Wh[(size_t)VV*KTOT];
__device__ __nv_bfloat16 g_Wl[(size_t)VV*KTOT];

extern __shared__ char dynsmem[];

#define SWZ(o) ((o) ^ (((o) >> 3) & 0x70))

__device__ __forceinline__ uint32_t s2u(const void* p) {
    uint32_t a;
    asm("{ .reg .u64 t; cvta.to.shared.u64 t, %1; cvt.u32.u64 %0, t; }" : "=r"(a) : "l"(p));
    return a;
}
__device__ __forceinline__ void cp16(uint32_t smem, const void* g) {
    asm volatile("cp.async.cg.shared.global [%0], [%1], 16;" :: "r"(smem), "l"(g));
}
#define CP_COMMIT() asm volatile("cp.async.commit_group;" ::: "memory")
#define CP_WAIT1()  asm volatile("cp.async.wait_group 1;" ::: "memory")
#define CP_WAIT0()  asm volatile("cp.async.wait_group 0;" ::: "memory")

__device__ __forceinline__ void ldsm4(uint32_t* r, uint32_t addr) {
    asm volatile("ldmatrix.sync.aligned.m8n8.x4.shared.b16 {%0,%1,%2,%3}, [%4];"
        : "=r"(r[0]), "=r"(r[1]), "=r"(r[2]), "=r"(r[3]) : "r"(addr));
}
__device__ __forceinline__ void mma16816(float* d, const uint32_t* a, const uint32_t* b) {
    asm volatile(
        "mma.sync.aligned.m16n8k16.row.col.f32.bf16.bf16.f32 "
        "{%0,%1,%2,%3}, {%4,%5,%6,%7}, {%8,%9}, {%0,%1,%2,%3};"
        : "+f"(d[0]), "+f"(d[1]), "+f"(d[2]), "+f"(d[3])
        : "r"(a[0]), "r"(a[1]), "r"(a[2]), "r"(a[3]), "r"(b[0]), "r"(b[1]));
}

// ---- init / gather ----
__global__ void init_state(const float* __restrict__ hidden, const float* __restrict__ cell,
                           float* h0, float* h1, float* c0, float* c1, int* bar) {
    int idx = blockIdx.x * blockDim.x + threadIdx.x;
    if (idx < 2*TT) bar[idx] = 0;
    if (idx >= HH*BB) return;
    int j = idx >> 5, b = idx & 31;
    int src = b * HH + j;
    h0[idx] = hidden[src];  h1[idx] = hidden[HH*BB + src];
    c0[idx] = cell[src];    c1[idx] = cell[HH*BB + src];
}
__global__ void gather_emb(const int* __restrict__ tgt, const float* __restrict__ emb,
                           float* __restrict__ x) {
    int m = blockIdx.x, r = tgt[m];
    reinterpret_cast<float4*>(x + (size_t)m * HH)[threadIdx.x] =
        reinterpret_cast<const float4*>(emb + (size_t)r * HH)[threadIdx.x];
}

// ---- SGEMM for input projections, transposed store C[n][m] ----
__global__ __launch_bounds__(256)
void sgemm_nt_t(const float* __restrict__ A, const float* __restrict__ B,
                float* __restrict__ C,
                const float* __restrict__ bias0, const float* __restrict__ bias1) {
    __shared__ float As[8][128], Bs[8][128];
    int tid = threadIdx.x, tx = tid & 15, ty = tid >> 4;
    int bm = blockIdx.y * 128, bn = blockIdx.x * 128;
    int lr = tid >> 1, lc = (tid & 1) * 4;
    const float* Ap = A + (size_t)(bm + lr) * HH + lc;
    const float* Bp = B + (size_t)(bn + lr) * HH + lc;
    float acc[8][8];
    #pragma unroll
    for (int i = 0; i < 8; i++)
        #pragma unroll
        for (int j = 0; j < 8; j++) acc[i][j] = 0.f;
    float4 a4 = *reinterpret_cast<const float4*>(Ap);
    float4 b4 = *reinterpret_cast<const float4*>(Bp);
    for (int k0 = 0; k0 < HH; k0 += 8) {
        As[lc+0][lr]=a4.x; As[lc+1][lr]=a4.y; As[lc+2][lr]=a4.z; As[lc+3][lr]=a4.w;
        Bs[lc+0][lr]=b4.x; Bs[lc+1][lr]=b4.y; Bs[lc+2][lr]=b4.z; Bs[lc+3][lr]=b4.w;
        __syncthreads();
        if (k0 + 8 < HH) {
            a4 = *reinterpret_cast<const float4*>(Ap + k0 + 8);
            b4 = *reinterpret_cast<const float4*>(Bp + k0 + 8);
        }
        #pragma unroll
        for (int kk = 0; kk < 8; kk++) {
            float ra[8], rb[8];
            *reinterpret_cast<float4*>(&ra[0]) = *reinterpret_cast<const float4*>(&As[kk][ty*8]);
            *reinterpret_cast<float4*>(&ra[4]) = *reinterpret_cast<const float4*>(&As[kk][ty*8+4]);
            *reinterpret_cast<float4*>(&rb[0]) = *reinterpret_cast<const float4*>(&Bs[kk][tx*8]);
            *reinterpret_cast<float4*>(&rb[4]) = *reinterpret_cast<const float4*>(&Bs[kk][tx*8+4]);
            #pragma unroll
            for (int i = 0; i < 8; i++)
                #pragma unroll
                for (int j = 0; j < 8; j++) acc[i][j] = fmaf(ra[i], rb[j], acc[i][j]);
        }
        __syncthreads();
    }
    #pragma unroll
    for (int i = 0; i < 8; i++) {
        int r = bm + ty*8 + i;
        #pragma unroll
        for (int j = 0; j < 8; j++) {
            int n = bn + tx*8 + j;
            C[(size_t)n * MROWS + r] = acc[i][j] + bias0[n] + bias1[n];
        }
    }
}

// ---- persistent LSTM v2: split-K across warp halves ------------------------
// 128 CTAs x 256 threads. Warp w: jl = w&3, half = w>>2 (k in [half*256, half*256+256)).
// CTA owns h-columns {4*cta .. 4*cta+3}. Dual accumulators per gate for ILP.
__device__ __forceinline__ float sigmoidf_(float x) { return 1.f / (1.f + expf(-x)); }

__global__ __launch_bounds__(256)
void lstm_persist(const float* __restrict__ xwT, const float* __restrict__ W_hh,
                  float* __restrict__ hbuf, float* __restrict__ cbuf,
                  float* __restrict__ ys, int* __restrict__ bar) {
    float* smemf = reinterpret_cast<float*>(dynsmem);
    float* Ws = smemf;                 // 16 rows x 512 = 8192 floats
    float* Hs = smemf + 4*4*HH;        // 512 x 32 = 16384 floats
    float* Ps = Hs + HH*BB;            // partials: [gate][jl][b] = 512 floats

    int tid = threadIdx.x, w = tid >> 5, b = tid & 31, cta = blockIdx.x;
    int half = w >> 2, jl = w & 3;
    int jg = cta * 4 + jl;

    // load 16 W rows (2048 float4) with 256 threads
    #pragma unroll
    for (int it = 0; it < 8; it++) {
        int idx = tid + it * 256;            // 0..2047
        int row = idx >> 7, col4 = idx & 127;
        int g = row >> 2, j2 = row & 3;
        reinterpret_cast<float4*>(Ws)[row * 128 + col4] =
            reinterpret_cast<const float4*>(W_hh + (size_t)(g*HH + cta*4 + j2) * HH)[col4];
    }
    float creg = (half == 0) ? cbuf[jg*32 + b] : 0.f;
    __syncthreads();

    const float4* wi = reinterpret_cast<const float4*>(&Ws[(0*4 + jl) * HH]) + half*64;
    const float4* wf = reinterpret_cast<const float4*>(&Ws[(1*4 + jl) * HH]) + half*64;
    const float4* wg = reinterpret_cast<const float4*>(&Ws[(2*4 + jl) * HH]) + half*64;
    const float4* wo = reinterpret_cast<const float4*>(&Ws[(3*4 + jl) * HH]) + half*64;
    const float* Hh = Hs + half * 256 * 32;

    volatile int* vbar = (volatile int*)bar;

    for (int t = 0; t < TT; t++) {
        // stage h(t): 4096 float4 over 256 threads
        {
            const float4* hsrc = reinterpret_cast<const float4*>(hbuf + (t & 1) * HH*BB);
            float4* hdst = reinterpret_cast<float4*>(Hs);
            #pragma unroll
            for (int i = 0; i < 16; i++)
                hdst[tid + (i << 8)] = __ldcg(hsrc + tid + (i << 8));
        }
        __syncthreads();

        int m = t*32 + b;
        float ai0 = 0.f, af0 = 0.f, ag0 = 0.f, ao0 = 0.f;
        float ai1 = 0.f, af1 = 0.f, ag1 = 0.f, ao1 = 0.f;
        if (half == 0) {
            ai0 = xwT[(size_t)(0*HH + jg) * MROWS + m];
            af0 = xwT[(size_t)(1*HH + jg) * MROWS + m];
            ag0 = xwT[(size_t)(2*HH + jg) * MROWS + m];
            ao0 = xwT[(size_t)(3*HH + jg) * MROWS + m];
        }

        #pragma unroll 8
        for (int k4 = 0; k4 < 64; k4 += 2) {
            // even k4 -> acc0
            {
                float4 vi = wi[k4], vf = wf[k4], vg = wg[k4], vo = wo[k4];
                int k = k4 << 2;
                float h0 = Hh[(k+0)*32 + b], h1 = Hh[(k+1)*32 + b];
                float h2 = Hh[(k+2)*32 + b], h3 = Hh[(k+3)*32 + b];
                ai0 = fmaf(vi.x,h0,ai0); af0 = fmaf(vf.x,h0,af0); ag0 = fmaf(vg.x,h0,ag0); ao0 = fmaf(vo.x,h0,ao0);
                ai0 = fmaf(vi.y,h1,ai0); af0 = fmaf(vf.y,h1,af0); ag0 = fmaf(vg.y,h1,ag0); ao0 = fmaf(vo.y,h1,ao0);
                ai0 = fmaf(vi.z,h2,ai0); af0 = fmaf(vf.z,h2,af0); ag0 = fmaf(vg.z,h2,ag0); ao0 = fmaf(vo.z,h2,ao0);
                ai0 = fmaf(vi.w,h3,ai0); af0 = fmaf(vf.w,h3,af0); ag0 = fmaf(vg.w,h3,ag0); ao0 = fmaf(vo.w,h3,ao0);
            }
            // odd k4 -> acc1
            {
                float4 vi = wi[k4+1], vf = wf[k4+1], vg = wg[k4+1], vo = wo[k4+1];
                int k = (k4+1) << 2;
                float h0 = Hh[(k+0)*32 + b], h1 = Hh[(k+1)*32 + b];
                float h2 = Hh[(k+2)*32 + b], h3 = Hh[(k+3)*32 + b];
                ai1 = fmaf(vi.x,h0,ai1); af1 = fmaf(vf.x,h0,af1); ag1 = fmaf(vg.x,h0,ag1); ao1 = fmaf(vo.x,h0,ao1);
                ai1 = fmaf(vi.y,h1,ai1); af1 = fmaf(vf.y,h1,af1); ag1 = fmaf(vg.y,h1,ag1); ao1 = fmaf(vo.y,h1,ao1);
                ai1 = fmaf(vi.z,h2,ai1); af1 = fmaf(vf.z,h2,af1); ag1 = fmaf(vg.z,h2,ag1); ao1 = fmaf(vo.z,h2,ao1);
                ai1 = fmaf(vi.w,h3,ai1); af1 = fmaf(vf.w,h3,af1); ag1 = fmaf(vg.w,h3,ag1); ao1 = fmaf(vo.w,h3,ao1);
            }
        }
        float ai = ai0 + ai1, af = af0 + af1, ag = ag0 + ag1, ao = ao0 + ao1;

        if (half == 1) {
            Ps[0*128 + jl*32 + b] = ai;
            Ps[1*128 + jl*32 + b] = af;
            Ps[2*128 + jl*32 + b] = ag;
            Ps[3*128 + jl*32 + b] = ao;
        }
        __syncthreads();
        if (half == 0) {
            ai += Ps[0*128 + jl*32 + b];
            af += Ps[1*128 + jl*32 + b];
            ag += Ps[2*128 + jl*32 + b];
            ao += Ps[3*128 + jl*32 + b];
            float ig = sigmoidf_(ai), fg = sigmoidf_(af);
            float gg = tanhf(ag),    og = sigmoidf_(ao);
            float c_new = fmaf(fg, creg, ig * gg);
            float h_new = og * tanhf(c_new);
            creg = c_new;
            hbuf[((t+1)&1) * HH*BB + jg*32 + b] = h_new;
            ys[(size_t)m * HH + jg] = h_new;
            if (t == TT-1) cbuf[jg*32 + b] = creg;
            __threadfence();
        }
        __syncthreads();
        if (tid == 0) {
            atomicAdd(&bar[t], 1);
            while (vbar[t] < (int)gridDim.x) { __nanosleep(32); }
            __threadfence();
        }
        __syncthreads();
    }
}

// ---- ctx: exact softmax shortcut = masked mean over S ----
__global__ void ctx_kernel(const float* __restrict__ enc, const int* __restrict__ src_mask,
                           float* __restrict__ ctx) {
    int b = blockIdx.x, h = threadIdx.x;
    float s_un = 0.f, s_all = 0.f; int cnt = 0;
    #pragma unroll 4
    for (int s = 0; s < SS; s++) {
        float v = enc[((size_t)s * BB + b) * HH + h];
        s_all += v;
        if (src_mask[s * BB + b] == 0) { s_un += v; cnt++; }
    }
    ctx[b * HH + h] = (cnt > 0) ? (s_un / (float)cnt) : (s_all / (float)SS);
}

// ---- fp32 -> bf16 hi/lo split converters ----
__device__ __forceinline__ void split8(const float* src, __nv_bfloat16* hi, __nv_bfloat16* lo) {
    float4 f0 = *reinterpret_cast<const float4*>(src);
    float4 f1 = *reinterpret_cast<const float4*>(src + 4);
    float fv[8] = {f0.x,f0.y,f0.z,f0.w,f1.x,f1.y,f1.z,f1.w};
    __nv_bfloat16 h8[8], l8[8];
    #pragma unroll
    for (int q = 0; q < 8; q++) {
        h8[q] = __float2bfloat16_rn(fv[q]);
        l8[q] = __float2bfloat16_rn(fv[q] - __bfloat162float(h8[q]));
    }
    *reinterpret_cast<uint4*>(hi) = *reinterpret_cast<uint4*>(h8);
    *reinterpret_cast<uint4*>(lo) = *reinterpret_cast<uint4*>(l8);
}
__global__ void conv_w(const float* __restrict__ W2, __nv_bfloat16* hi, __nv_bfloat16* lo) {
    size_t i = ((size_t)blockIdx.x * blockDim.x + threadIdx.x) * 8;
    split8(W2 + i, hi + i, lo + i);
}
__global__ void conv_a(const float* __restrict__ dec, const float* __restrict__ ctx,
                       __nv_bfloat16* hi, __nv_bfloat16* lo) {
    int m = blockIdx.x, t8 = threadIdx.x * 8;
    const float* src = (t8 < HH) ? dec + (size_t)m*HH + t8
                                 : ctx + (size_t)(m & 31)*HH + (t8 - HH);
    size_t o = (size_t)m * KTOT + t8;
    split8(src, hi + o, lo + o);
}

// ---- mma.sync logits GEMM (unchanged from passing R9 kernel) ----
#define CHUNKS 16
#define PLANE 16384
#define BUFSTR (4*PLANE)                 // 64 KB
#define GSMEM  (2*BUFSTR)                // 128 KB

__global__ __launch_bounds__(256, 1)
void gemm_logits_mma(const __nv_bfloat16* __restrict__ Ah, const __nv_bfloat16* __restrict__ Al,
                     const __nv_bfloat16* __restrict__ Bh, const __nv_bfloat16* __restrict__ Bl,
                     float* __restrict__ out) {
    uint32_t sb = s2u(dynsmem);
    int tid = threadIdx.x, wid = tid >> 5, lane = tid & 31;
    int bm = blockIdx.x * 128, bn = blockIdx.y * 128;
    int wm = (wid & 3) * 32;
    int wn = (wid >> 2) * 64;

    float acc[2][8][4];
    #pragma unroll
    for (int mt = 0; mt < 2; mt++)
        #pragma unroll
        for (int nt = 0; nt < 8; nt++)
            #pragma unroll
            for (int q = 0; q < 4; q++) acc[mt][nt][q] = 0.f;

    const __nv_bfloat16* gsrc[4] = {Ah, Al, Bh, Bl};

    auto fill = [&](int c, int buf) {
        uint32_t base = sb + buf * BUFSTR;
        #pragma unroll
        for (int it = 0; it < 16; it++) {
            int i = tid + it * 256;
            int p = i >> 10, j = i & 1023;
            int r = j >> 3, seg = j & 7;
            int grow = (p < 2) ? (bm + r) : (bn + r);
            const __nv_bfloat16* g = gsrc[p] + ((size_t)grow << 10) + (c << 6) + (seg << 3);
            cp16(base + p * PLANE + SWZ((uint32_t)(r * 128 + seg * 16)), g);
        }
        CP_COMMIT();
    };

    fill(0, 0);
    for (int c = 0; c < CHUNKS; c++) {
        int buf = c & 1;
        if (c + 1 < CHUNKS) { fill(c + 1, buf ^ 1); CP_WAIT1(); }
        else                { CP_WAIT0(); }
        __syncthreads();

        uint32_t base = sb + buf * BUFSTR;
        #pragma unroll
        for (int kk = 0; kk < 4; kk++) {
            uint32_t afh[2][4], afl[2][4];
            #pragma unroll
            for (int mt = 0; mt < 2; mt++) {
                int r = wm + mt * 16 + (lane & 15);
                uint32_t off = SWZ((uint32_t)(r * 128 + kk * 32 + (lane >> 4) * 16));
                ldsm4(afh[mt], base + 0 * PLANE + off);
                ldsm4(afl[mt], base + 1 * PLANE + off);
            }
            uint32_t bfh[4][4], bfl[4][4];
            #pragma unroll
            for (int np = 0; np < 4; np++) {
                int nrow = wn + np * 16 + (lane & 7) + ((lane >> 4) << 3);
                uint32_t off = SWZ((uint32_t)(nrow * 128 + kk * 32 + ((lane >> 3) & 1) * 16));
                ldsm4(bfh[np], base + 2 * PLANE + off);
                ldsm4(bfl[np], base + 3 * PLANE + off);
            }
            #pragma unroll
            for (int mt = 0; mt < 2; mt++)
                #pragma unroll
                for (int nt = 0; nt < 8; nt++) {
                    const uint32_t* bh = &bfh[nt >> 1][(nt & 1) * 2];
                    const uint32_t* bl = &bfl[nt >> 1][(nt & 1) * 2];
                    mma16816(acc[mt][nt], afh[mt], bh);
                    mma16816(acc[mt][nt], afh[mt], bl);
                    mma16816(acc[mt][nt], afl[mt], bh);
                }
        }
        __syncthreads();
    }

    #pragma unroll
    for (int mt = 0; mt < 2; mt++) {
        int r0 = bm + wm + mt * 16 + (lane >> 2);
        #pragma unroll
        for (int nt = 0; nt < 8; nt++) {
            int cidx = bn + wn + nt * 8 + (lane & 3) * 2;
            *reinterpret_cast<float2*>(out + (size_t)r0 * VV + cidx) =
                make_float2(acc[mt][nt][0], acc[mt][nt][1]);
            *reinterpret_cast<float2*>(out + (size_t)(r0 + 8) * VV + cidx) =
                make_float2(acc[mt][nt][2], acc[mt][nt][3]);
        }
    }
}

// ---- tail: hs / cs ----
__global__ void tail_kernel(const float* __restrict__ ys0, const float* __restrict__ ys1,
                            const float* __restrict__ c0, const float* __restrict__ c1,
                            float* __restrict__ out) {
    int idx = blockIdx.x * blockDim.x + threadIdx.x;
    if (idx >= 4*HH*BB) return;
    int seg = idx >> 14, i = idx & 16383;
    int b = i >> 9, j = i & 511;
    float v;
    if      (seg == 0) v = ys0[((size_t)(TT-1)*BB + b) * HH + j];
    else if (seg == 1) v = ys1[((size_t)(TT-1)*BB + b) * HH + j];
    else if (seg == 2) v = c0[j*32 + b];
    else               v = c1[j*32 + b];
    out[(size_t)MROWS * VV + idx] = v;
}

// ---- launch ----
extern "C" void kernel_launch(void* const* d_in, const int* in_sizes, int n_in,
                              void* d_out, int out_size) {
    (void)in_sizes; (void)n_in; (void)out_size;
    const int*   tgt     = (const int*)  d_in[0];
    const float* hidden  = (const float*)d_in[1];
    const float* cell    = (const float*)d_in[2];
    const float* enc     = (const float*)d_in[3];
    const int*   srcmask = (const int*)  d_in[4];
    const float* emb     = (const float*)d_in[5];
    const float* Wih0    = (const float*)d_in[6];
    const float* Whh0    = (const float*)d_in[7];
    const float* bih0    = (const float*)d_in[8];
    const float* bhh0    = (const float*)d_in[9];
    const float* Wih1    = (const float*)d_in[10];
    const float* Whh1    = (const float*)d_in[11];
    const float* bih1    = (const float*)d_in[12];
    const float* bhh1    = (const float*)d_in[13];
    // d_in[14] = W1: provably irrelevant (softmax shortcut)
    const float* W2      = (const float*)d_in[15];
    float* out = (float*)d_out;

    float *p_x, *p_xw, *p_ys0, *p_ys1, *p_h0, *p_h1, *p_c0, *p_c1, *p_ctx;
    __nv_bfloat16 *p_Ah, *p_Al, *p_Wh, *p_Wl;
    int *p_bar;
    cudaGetSymbolAddress((void**)&p_x,   g_x);
    cudaGetSymbolAddress((void**)&p_xw,  g_xw);
    cudaGetSymbolAddress((void**)&p_ys0, g_ys0);
    cudaGetSymbolAddress((void**)&p_ys1, g_ys1);
    cudaGetSymbolAddress((void**)&p_h0,  g_h0);
    cudaGetSymbolAddress((void**)&p_h1,  g_h1);
    cudaGetSymbolAddress((void**)&p_c0,  g_c0);
    cudaGetSymbolAddress((void**)&p_c1,  g_c1);
    cudaGetSymbolAddress((void**)&p_ctx, g_ctx);
    cudaGetSymbolAddress((void**)&p_Ah,  g_Ah);
    cudaGetSymbolAddress((void**)&p_Al,  g_Al);
    cudaGetSymbolAddress((void**)&p_Wh,  g_Wh);
    cudaGetSymbolAddress((void**)&p_Wl,  g_Wl);
    cudaGetSymbolAddress((void**)&p_bar, g_bar);

    const int PERSIST_SMEM = (4*4*HH + HH*BB + 512) * sizeof(float);  // ~100 KB
    cudaFuncSetAttribute(lstm_persist, cudaFuncAttributeMaxDynamicSharedMemorySize, PERSIST_SMEM);
    cudaFuncSetAttribute(gemm_logits_mma, cudaFuncAttributeMaxDynamicSharedMemorySize, GSMEM);

    init_state<<<64, 256>>>(hidden, cell, p_h0, p_h1, p_c0, p_c1, p_bar);
    gather_emb<<<MROWS, 128>>>(tgt, emb, p_x);
    conv_w<<<(int)(((size_t)VV*KTOT)/8/256), 256>>>(W2, p_Wh, p_Wl);

    sgemm_nt_t<<<dim3(G4H/128, MROWS/128), 256>>>(p_x, Wih0, p_xw, bih0, bhh0);
    lstm_persist<<<128, 256, PERSIST_SMEM>>>(p_xw, Whh0, p_h0, p_c0, p_ys0, p_bar);
    sgemm_nt_t<<<dim3(G4H/128, MROWS/128), 256>>>(p_ys0, Wih1, p_xw, bih1, bhh1);
    lstm_persist<<<128, 256, PERSIST_SMEM>>>(p_xw, Whh1, p_h1, p_c1, p_ys1, p_bar + TT);

    ctx_kernel<<<BB, HH>>>(enc, srcmask, p_ctx);
    conv_a<<<MROWS, 128>>>(p_ys1, p_ctx, p_Ah, p_Al);

    gemm_logits_mma<<<dim3(MROWS/128, VV/128), 256, GSMEM>>>(p_Ah, p_Al, p_Wh, p_Wl, out);

    tail_kernel<<<64, 1024>>>(p_ys0, p_ys1, p_c0, p_c1, out);
}

// round 13
// speedup vs baseline: 1.7422x; 1.1069x over previous
#include <cuda_runtime.h>
#include <cuda_bf16.h>
#include <math.h>
#include <stdint.h>

#define TT 64
#define BB 32
#define HH 512
#define VV 32000
#define SS 64
#define MROWS (TT*BB)      // 2048
#define G4H (4*HH)         // 2048
#define KTOT 1024

// ---- static scratch ----
__device__ float g_x   [MROWS*HH];
__device__ float g_xw  [MROWS*G4H];          // input proj, transposed [gate_row][m]
__device__ float g_ys0 [MROWS*HH];
__device__ float g_ys1 [MROWS*HH];
__device__ float g_h0  [2][HH*BB];
__device__ float g_h1  [2][HH*BB];
__device__ float g_c0  [HH*BB];
__device__ float g_c1  [HH*BB];
__device__ float g_ctx [BB*HH];
__device__ int   g_bar [2*TT];
__device__ __nv_bfloat16 g_Ah[MROWS*KTOT];
__device__ __nv_bfloat16 g_Al[MROWS*KTOT];
__device__ __nv_bfloat16 g_Wh[(size_t)VV*KTOT];
__device__ __nv_bfloat16 g_Wl[(size_t)VV*KTOT];
__device__ __nv_bfloat16 g_xh[MROWS*HH];     // x / ys0 split hi
__device__ __nv_bfloat16 g_xl[MROWS*HH];
__device__ __nv_bfloat16 g_wih_h[G4H*HH];    // Wih split hi
__device__ __nv_bfloat16 g_wih_l[G4H*HH];

extern __shared__ char dynsmem[];

#define SWZ(o) ((o) ^ (((o) >> 3) & 0x70))

__device__ __forceinline__ uint32_t s2u(const void* p) {
    uint32_t a;
    asm("{ .reg .u64 t; cvta.to.shared.u64 t, %1; cvt.u32.u64 %0, t; }" : "=r"(a) : "l"(p));
    return a;
}
__device__ __forceinline__ void cp16(uint32_t smem, const void* g) {
    asm volatile("cp.async.cg.shared.global [%0], [%1], 16;" :: "r"(smem), "l"(g));
}
#define CP_COMMIT() asm volatile("cp.async.commit_group;" ::: "memory")
#define CP_WAIT1()  asm volatile("cp.async.wait_group 1;" ::: "memory")
#define CP_WAIT0()  asm volatile("cp.async.wait_group 0;" ::: "memory")

__device__ __forceinline__ void ldsm4(uint32_t* r, uint32_t addr) {
    asm volatile("ldmatrix.sync.aligned.m8n8.x4.shared.b16 {%0,%1,%2,%3}, [%4];"
        : "=r"(r[0]), "=r"(r[1]), "=r"(r[2]), "=r"(r[3]) : "r"(addr));
}
__device__ __forceinline__ void mma16816(float* d, const uint32_t* a, const uint32_t* b) {
    asm volatile(
        "mma.sync.aligned.m16n8k16.row.col.f32.bf16.bf16.f32 "
        "{%0,%1,%2,%3}, {%4,%5,%6,%7}, {%8,%9}, {%0,%1,%2,%3};"
        : "+f"(d[0]), "+f"(d[1]), "+f"(d[2]), "+f"(d[3])
        : "r"(a[0]), "r"(a[1]), "r"(a[2]), "r"(a[3]), "r"(b[0]), "r"(b[1]));
}

// ---- init / gather ----
__global__ void init_state(const float* __restrict__ hidden, const float* __restrict__ cell,
                           float* h0, float* h1, float* c0, float* c1, int* bar) {
    int idx = blockIdx.x * blockDim.x + threadIdx.x;
    if (idx < 2*TT) bar[idx] = 0;
    if (idx >= HH*BB) return;
    int j = idx >> 5, b = idx & 31;
    int src = b * HH + j;
    h0[idx] = hidden[src];  h1[idx] = hidden[HH*BB + src];
    c0[idx] = cell[src];    c1[idx] = cell[HH*BB + src];
}
__global__ void gather_emb(const int* __restrict__ tgt, const float* __restrict__ emb,
                           float* __restrict__ x) {
    int m = blockIdx.x, r = tgt[m];
    reinterpret_cast<float4*>(x + (size_t)m * HH)[threadIdx.x] =
        reinterpret_cast<const float4*>(emb + (size_t)r * HH)[threadIdx.x];
}

// ---- fp32 -> bf16 hi/lo split (flat) ----
__device__ __forceinline__ void split8(const float* src, __nv_bfloat16* hi, __nv_bfloat16* lo) {
    float4 f0 = *reinterpret_cast<const float4*>(src);
    float4 f1 = *reinterpret_cast<const float4*>(src + 4);
    float fv[8] = {f0.x,f0.y,f0.z,f0.w,f1.x,f1.y,f1.z,f1.w};
    __nv_bfloat16 h8[8], l8[8];
    #pragma unroll
    for (int q = 0; q < 8; q++) {
        h8[q] = __float2bfloat16_rn(fv[q]);
        l8[q] = __float2bfloat16_rn(fv[q] - __bfloat162float(h8[q]));
    }
    *reinterpret_cast<uint4*>(hi) = *reinterpret_cast<uint4*>(h8);
    *reinterpret_cast<uint4*>(lo) = *reinterpret_cast<uint4*>(l8);
}
__global__ void conv_flat(const float* __restrict__ src, __nv_bfloat16* hi, __nv_bfloat16* lo) {
    size_t i = ((size_t)blockIdx.x * blockDim.x + threadIdx.x) * 8;
    split8(src + i, hi + i, lo + i);
}
__global__ void conv_a(const float* __restrict__ dec, const float* __restrict__ ctx,
                       __nv_bfloat16* hi, __nv_bfloat16* lo) {
    int m = blockIdx.x, t8 = threadIdx.x * 8;
    const float* src = (t8 < HH) ? dec + (size_t)m*HH + t8
                                 : ctx + (size_t)(m & 31)*HH + (t8 - HH);
    size_t o = (size_t)m * KTOT + t8;
    split8(src, hi + o, lo + o);
}

// ---- mma input-projection GEMM: xwT[n][m] = sum_k A[m][k]Wih[n][k] + b0[n]+b1[n]
// M=N=2048, K=512 (8 chunks of 64). 3-pass bf16 split. CTA 128x128, 8 warps.
#define PLANE 16384
#define BUFSTR (4*PLANE)
#define GSMEM  (2*BUFSTR)      // 128 KB

__global__ __launch_bounds__(256, 1)
void gemm_xw_mma(const __nv_bfloat16* __restrict__ Ah, const __nv_bfloat16* __restrict__ Al,
                 const __nv_bfloat16* __restrict__ Bh, const __nv_bfloat16* __restrict__ Bl,
                 float* __restrict__ C,
                 const float* __restrict__ bias0, const float* __restrict__ bias1) {
    uint32_t sb = s2u(dynsmem);
    int tid = threadIdx.x, wid = tid >> 5, lane = tid & 31;
    int bm = blockIdx.x * 128, bn = blockIdx.y * 128;
    int wm = (wid & 3) * 32, wn = (wid >> 2) * 64;

    float acc[2][8][4];
    #pragma unroll
    for (int mt = 0; mt < 2; mt++)
        #pragma unroll
        for (int nt = 0; nt < 8; nt++)
            #pragma unroll
            for (int q = 0; q < 4; q++) acc[mt][nt][q] = 0.f;

    const __nv_bfloat16* gsrc[4] = {Ah, Al, Bh, Bl};
    auto fill = [&](int c, int buf) {
        uint32_t base = sb + buf * BUFSTR;
        #pragma unroll
        for (int it = 0; it < 16; it++) {
            int i = tid + it * 256;
            int p = i >> 10, j = i & 1023;
            int r = j >> 3, seg = j & 7;
            int grow = (p < 2) ? (bm + r) : (bn + r);
            const __nv_bfloat16* g = gsrc[p] + ((size_t)grow << 9) + (c << 6) + (seg << 3);
            cp16(base + p * PLANE + SWZ((uint32_t)(r * 128 + seg * 16)), g);
        }
        CP_COMMIT();
    };

    fill(0, 0);
    for (int c = 0; c < 8; c++) {
        int buf = c & 1;
        if (c + 1 < 8) { fill(c + 1, buf ^ 1); CP_WAIT1(); }
        else           { CP_WAIT0(); }
        __syncthreads();
        uint32_t base = sb + buf * BUFSTR;
        #pragma unroll
        for (int kk = 0; kk < 4; kk++) {
            uint32_t afh[2][4], afl[2][4];
            #pragma unroll
            for (int mt = 0; mt < 2; mt++) {
                int r = wm + mt * 16 + (lane & 15);
                uint32_t off = SWZ((uint32_t)(r * 128 + kk * 32 + (lane >> 4) * 16));
                ldsm4(afh[mt], base + 0 * PLANE + off);
                ldsm4(afl[mt], base + 1 * PLANE + off);
            }
            uint32_t bfh[4][4], bfl[4][4];
            #pragma unroll
            for (int np = 0; np < 4; np++) {
                int nrow = wn + np * 16 + (lane & 7) + ((lane >> 4) << 3);
                uint32_t off = SWZ((uint32_t)(nrow * 128 + kk * 32 + ((lane >> 3) & 1) * 16));
                ldsm4(bfh[np], base + 2 * PLANE + off);
                ldsm4(bfl[np], base + 3 * PLANE + off);
            }
            #pragma unroll
            for (int mt = 0; mt < 2; mt++)
                #pragma unroll
                for (int nt = 0; nt < 8; nt++) {
                    const uint32_t* bh = &bfh[nt >> 1][(nt & 1) * 2];
                    const uint32_t* bl = &bfl[nt >> 1][(nt & 1) * 2];
                    mma16816(acc[mt][nt], afh[mt], bh);
                    mma16816(acc[mt][nt], afh[mt], bl);
                    mma16816(acc[mt][nt], afl[mt], bh);
                }
        }
        __syncthreads();
    }
    // transposed epilogue: C[n][m] + biases
    #pragma unroll
    for (int mt = 0; mt < 2; mt++) {
        int r0 = bm + wm + mt * 16 + (lane >> 2);
        #pragma unroll
        for (int nt = 0; nt < 8; nt++) {
            int n0 = bn + wn + nt * 8 + (lane & 3) * 2;
            float b0 = bias0[n0] + bias1[n0];
            float b1 = bias0[n0+1] + bias1[n0+1];
            C[(size_t)n0     * MROWS + r0]     = acc[mt][nt][0] + b0;
            C[(size_t)(n0+1) * MROWS + r0]     = acc[mt][nt][1] + b1;
            C[(size_t)n0     * MROWS + r0 + 8] = acc[mt][nt][2] + b0;
            C[(size_t)(n0+1) * MROWS + r0 + 8] = acc[mt][nt][3] + b1;
        }
    }
}

// ---- persistent LSTM v3: split-K x4 (512 threads) ---------------------------
// 128 CTAs x 512 threads. warp w: jl = w&3, quarter q = w>>2 (k in [q*128, q*128+128)).
__device__ __forceinline__ float sigmoidf_(float x) { return 1.f / (1.f + expf(-x)); }

__global__ __launch_bounds__(512)
void lstm_persist(const float* __restrict__ xwT, const float* __restrict__ W_hh,
                  float* __restrict__ hbuf, float* __restrict__ cbuf,
                  float* __restrict__ ys, int* __restrict__ bar) {
    float* smemf = reinterpret_cast<float*>(dynsmem);
    float* Ws = smemf;                 // 16 x 512 = 8192 floats
    float* Hs = smemf + 4*4*HH;        // 512 x 32 = 16384 floats
    float* Ps = Hs + HH*BB;            // partials [3][4 gates][4 jl][32 b] = 1536

    int tid = threadIdx.x, w = tid >> 5, b = tid & 31, cta = blockIdx.x;
    int q = w >> 2, jl = w & 3;
    int jg = cta * 4 + jl;

    // load 16 W rows (2048 float4) with 512 threads
    #pragma unroll
    for (int it = 0; it < 4; it++) {
        int idx = tid + it * 512;
        int row = idx >> 7, col4 = idx & 127;
        int g = row >> 2, j2 = row & 3;
        reinterpret_cast<float4*>(Ws)[row * 128 + col4] =
            reinterpret_cast<const float4*>(W_hh + (size_t)(g*HH + cta*4 + j2) * HH)[col4];
    }
    float creg = (q == 0) ? cbuf[jg*32 + b] : 0.f;
    __syncthreads();

    const float4* wi = reinterpret_cast<const float4*>(&Ws[(0*4 + jl) * HH]) + q*32;
    const float4* wf = reinterpret_cast<const float4*>(&Ws[(1*4 + jl) * HH]) + q*32;
    const float4* wg = reinterpret_cast<const float4*>(&Ws[(2*4 + jl) * HH]) + q*32;
    const float4* wo = reinterpret_cast<const float4*>(&Ws[(3*4 + jl) * HH]) + q*32;
    const float* Hh = Hs + q * 128 * 32;

    volatile int* vbar = (volatile int*)bar;

    for (int t = 0; t < TT; t++) {
        {   // stage h(t): 4096 float4 over 512 threads
            const float4* hsrc = reinterpret_cast<const float4*>(hbuf + (t & 1) * HH*BB);
            float4* hdst = reinterpret_cast<float4*>(Hs);
            #pragma unroll
            for (int i = 0; i < 8; i++)
                hdst[tid + (i << 9)] = __ldcg(hsrc + tid + (i << 9));
        }
        __syncthreads();

        int m = t*32 + b;
        float ai0 = 0.f, af0 = 0.f, ag0 = 0.f, ao0 = 0.f;
        float ai1 = 0.f, af1 = 0.f, ag1 = 0.f, ao1 = 0.f;
        if (q == 0) {
            ai0 = xwT[(size_t)(0*HH + jg) * MROWS + m];
            af0 = xwT[(size_t)(1*HH + jg) * MROWS + m];
            ag0 = xwT[(size_t)(2*HH + jg) * MROWS + m];
            ao0 = xwT[(size_t)(3*HH + jg) * MROWS + m];
        }

        #pragma unroll 8
        for (int k4 = 0; k4 < 32; k4 += 2) {
            {
                float4 vi = wi[k4], vf = wf[k4], vg = wg[k4], vo = wo[k4];
                int k = k4 << 2;
                float h0 = Hh[(k+0)*32 + b], h1 = Hh[(k+1)*32 + b];
                float h2 = Hh[(k+2)*32 + b], h3 = Hh[(k+3)*32 + b];
                ai0 = fmaf(vi.x,h0,ai0); af0 = fmaf(vf.x,h0,af0); ag0 = fmaf(vg.x,h0,ag0); ao0 = fmaf(vo.x,h0,ao0);
                ai0 = fmaf(vi.y,h1,ai0); af0 = fmaf(vf.y,h1,af0); ag0 = fmaf(vg.y,h1,ag0); ao0 = fmaf(vo.y,h1,ao0);
                ai0 = fmaf(vi.z,h2,ai0); af0 = fmaf(vf.z,h2,af0); ag0 = fmaf(vg.z,h2,ag0); ao0 = fmaf(vo.z,h2,ao0);
                ai0 = fmaf(vi.w,h3,ai0); af0 = fmaf(vf.w,h3,af0); ag0 = fmaf(vg.w,h3,ag0); ao0 = fmaf(vo.w,h3,ao0);
            }
            {
                float4 vi = wi[k4+1], vf = wf[k4+1], vg = wg[k4+1], vo = wo[k4+1];
                int k = (k4+1) << 2;
                float h0 = Hh[(k+0)*32 + b], h1 = Hh[(k+1)*32 + b];
                float h2 = Hh[(k+2)*32 + b], h3 = Hh[(k+3)*32 + b];
                ai1 = fmaf(vi.x,h0,ai1); af1 = fmaf(vf.x,h0,af1); ag1 = fmaf(vg.x,h0,ag1); ao1 = fmaf(vo.x,h0,ao1);
                ai1 = fmaf(vi.y,h1,ai1); af1 = fmaf(vf.y,h1,af1); ag1 = fmaf(vg.y,h1,ag1); ao1 = fmaf(vo.y,h1,ao1);
                ai1 = fmaf(vi.z,h2,ai1); af1 = fmaf(vf.z,h2,af1); ag1 = fmaf(vg.z,h2,ag1); ao1 = fmaf(vo.z,h2,ao1);
                ai1 = fmaf(vi.w,h3,ai1); af1 = fmaf(vf.w,h3,af1); ag1 = fmaf(vg.w,h3,ag1); ao1 = fmaf(vo.w,h3,ao1);
            }
        }
        float ai = ai0 + ai1, af = af0 + af1, ag = ag0 + ag1, ao = ao0 + ao1;

        if (q != 0) {
            int o = jl*32 + b;
            Ps[(q-1)*512 + 0*128 + o] = ai;
            Ps[(q-1)*512 + 1*128 + o] = af;
            Ps[(q-1)*512 + 2*128 + o] = ag;
            Ps[(q-1)*512 + 3*128 + o] = ao;
        }
        __syncthreads();
        if (q == 0) {
            int o = jl*32 + b;
            ai += Ps[0*512 + 0*128 + o] + Ps[1*512 + 0*128 + o] + Ps[2*512 + 0*128 + o];
            af += Ps[0*512 + 1*128 + o] + Ps[1*512 + 1*128 + o] + Ps[2*512 + 1*128 + o];
            ag += Ps[0*512 + 2*128 + o] + Ps[1*512 + 2*128 + o] + Ps[2*512 + 2*128 + o];
            ao += Ps[0*512 + 3*128 + o] + Ps[1*512 + 3*128 + o] + Ps[2*512 + 3*128 + o];
            float ig = sigmoidf_(ai), fg = sigmoidf_(af);
            float gg = tanhf(ag),    og = sigmoidf_(ao);
            float c_new = fmaf(fg, creg, ig * gg);
            float h_new = og * tanhf(c_new);
            creg = c_new;
            hbuf[((t+1)&1) * HH*BB + jg*32 + b] = h_new;
            ys[(size_t)m * HH + jg] = h_new;
            if (t == TT-1) cbuf[jg*32 + b] = creg;
            __threadfence();
        }
        __syncthreads();
        if (tid == 0) {
            atomicAdd(&bar[t], 1);
            while (vbar[t] < (int)gridDim.x) { __nanosleep(32); }
            __threadfence();
        }
        __syncthreads();
    }
}

// ---- ctx: exact softmax shortcut = masked mean over S ----
__global__ void ctx_kernel(const float* __restrict__ enc, const int* __restrict__ src_mask,
                           float* __restrict__ ctx) {
    int b = blockIdx.x, h = threadIdx.x;
    float s_un = 0.f, s_all = 0.f; int cnt = 0;
    #pragma unroll 4
    for (int s = 0; s < SS; s++) {
        float v = enc[((size_t)s * BB + b) * HH + h];
        s_all += v;
        if (src_mask[s * BB + b] == 0) { s_un += v; cnt++; }
    }
    ctx[b * HH + h] = (cnt > 0) ? (s_un / (float)cnt) : (s_all / (float)SS);
}

// ---- mma.sync logits GEMM (unchanged, validated) ----
#define CHUNKS 16
__global__ __launch_bounds__(256, 1)
void gemm_logits_mma(const __nv_bfloat16* __restrict__ Ah, const __nv_bfloat16* __restrict__ Al,
                     const __nv_bfloat16* __restrict__ Bh, const __nv_bfloat16* __restrict__ Bl,
                     float* __restrict__ out) {
    uint32_t sb = s2u(dynsmem);
    int tid = threadIdx.x, wid = tid >> 5, lane = tid & 31;
    int bm = blockIdx.x * 128, bn = blockIdx.y * 128;
    int wm = (wid & 3) * 32, wn = (wid >> 2) * 64;

    float acc[2][8][4];
    #pragma unroll
    for (int mt = 0; mt < 2; mt++)
        #pragma unroll
        for (int nt = 0; nt < 8; nt++)
            #pragma unroll
            for (int q = 0; q < 4; q++) acc[mt][nt][q] = 0.f;

    const __nv_bfloat16* gsrc[4] = {Ah, Al, Bh, Bl};
    auto fill = [&](int c, int buf) {
        uint32_t base = sb + buf * BUFSTR;
        #pragma unroll
        for (int it = 0; it < 16; it++) {
            int i = tid + it * 256;
            int p = i >> 10, j = i & 1023;
            int r = j >> 3, seg = j & 7;
            int grow = (p < 2) ? (bm + r) : (bn + r);
            const __nv_bfloat16* g = gsrc[p] + ((size_t)grow << 10) + (c << 6) + (seg << 3);
            cp16(base + p * PLANE + SWZ((uint32_t)(r * 128 + seg * 16)), g);
        }
        CP_COMMIT();
    };

    fill(0, 0);
    for (int c = 0; c < CHUNKS; c++) {
        int buf = c & 1;
        if (c + 1 < CHUNKS) { fill(c + 1, buf ^ 1); CP_WAIT1(); }
        else                { CP_WAIT0(); }
        __syncthreads();
        uint32_t base = sb + buf * BUFSTR;
        #pragma unroll
        for (int kk = 0; kk < 4; kk++) {
            uint32_t afh[2][4], afl[2][4];
            #pragma unroll
            for (int mt = 0; mt < 2; mt++) {
                int r = wm + mt * 16 + (lane & 15);
                uint32_t off = SWZ((uint32_t)(r * 128 + kk * 32 + (lane >> 4) * 16));
                ldsm4(afh[mt], base + 0 * PLANE + off);
                ldsm4(afl[mt], base + 1 * PLANE + off);
            }
            uint32_t bfh[4][4], bfl[4][4];
            #pragma unroll
            for (int np = 0; np < 4; np++) {
                int nrow = wn + np * 16 + (lane & 7) + ((lane >> 4) << 3);
                uint32_t off = SWZ((uint32_t)(nrow * 128 + kk * 32 + ((lane >> 3) & 1) * 16));
                ldsm4(bfh[np], base + 2 * PLANE + off);
                ldsm4(bfl[np], base + 3 * PLANE + off);
            }
            #pragma unroll
            for (int mt = 0; mt < 2; mt++)
                #pragma unroll
                for (int nt = 0; nt < 8; nt++) {
                    const uint32_t* bh = &bfh[nt >> 1][(nt & 1) * 2];
                    const uint32_t* bl = &bfl[nt >> 1][(nt & 1) * 2];
                    mma16816(acc[mt][nt], afh[mt], bh);
                    mma16816(acc[mt][nt], afh[mt], bl);
                    mma16816(acc[mt][nt], afl[mt], bh);
                }
        }
        __syncthreads();
    }
    #pragma unroll
    for (int mt = 0; mt < 2; mt++) {
        int r0 = bm + wm + mt * 16 + (lane >> 2);
        #pragma unroll
        for (int nt = 0; nt < 8; nt++) {
            int cidx = bn + wn + nt * 8 + (lane & 3) * 2;
            *reinterpret_cast<float2*>(out + (size_t)r0 * VV + cidx) =
                make_float2(acc[mt][nt][0], acc[mt][nt][1]);
            *reinterpret_cast<float2*>(out + (size_t)(r0 + 8) * VV + cidx) =
                make_float2(acc[mt][nt][2], acc[mt][nt][3]);
        }
    }
}

// ---- tail: hs / cs ----
__global__ void tail_kernel(const float* __restrict__ ys0, const float* __restrict__ ys1,
                            const float* __restrict__ c0, const float* __restrict__ c1,
                            float* __restrict__ out) {
    int idx = blockIdx.x * blockDim.x + threadIdx.x;
    if (idx >= 4*HH*BB) return;
    int seg = idx >> 14, i = idx & 16383;
    int b = i >> 9, j = i & 511;
    float v;
    if      (seg == 0) v = ys0[((size_t)(TT-1)*BB + b) * HH + j];
    else if (seg == 1) v = ys1[((size_t)(TT-1)*BB + b) * HH + j];
    else if (seg == 2) v = c0[j*32 + b];
    else               v = c1[j*32 + b];
    out[(size_t)MROWS * VV + idx] = v;
}

// ---- launch ----
extern "C" void kernel_launch(void* const* d_in, const int* in_sizes, int n_in,
                              void* d_out, int out_size) {
    (void)in_sizes; (void)n_in; (void)out_size;
    const int*   tgt     = (const int*)  d_in[0];
    const float* hidden  = (const float*)d_in[1];
    const float* cell    = (const float*)d_in[2];
    const float* enc     = (const float*)d_in[3];
    const int*   srcmask = (const int*)  d_in[4];
    const float* emb     = (const float*)d_in[5];
    const float* Wih0    = (const float*)d_in[6];
    const float* Whh0    = (const float*)d_in[7];
    const float* bih0    = (const float*)d_in[8];
    const float* bhh0    = (const float*)d_in[9];
    const float* Wih1    = (const float*)d_in[10];
    const float* Whh1    = (const float*)d_in[11];
    const float* bih1    = (const float*)d_in[12];
    const float* bhh1    = (const float*)d_in[13];
    // d_in[14] = W1: provably irrelevant (softmax shortcut)
    const float* W2      = (const float*)d_in[15];
    float* out = (float*)d_out;

    float *p_x, *p_xw, *p_ys0, *p_ys1, *p_h0, *p_h1, *p_c0, *p_c1, *p_ctx;
    __nv_bfloat16 *p_Ah, *p_Al, *p_Wh, *p_Wl, *p_xh, *p_xl, *p_wih_h, *p_wih_l;
    int *p_bar;
    cudaGetSymbolAddress((void**)&p_x,     g_x);
    cudaGetSymbolAddress((void**)&p_xw,    g_xw);
    cudaGetSymbolAddress((void**)&p_ys0,   g_ys0);
    cudaGetSymbolAddress((void**)&p_ys1,   g_ys1);
    cudaGetSymbolAddress((void**)&p_h0,    g_h0);
    cudaGetSymbolAddress((void**)&p_h1,    g_h1);
    cudaGetSymbolAddress((void**)&p_c0,    g_c0);
    cudaGetSymbolAddress((void**)&p_c1,    g_c1);
    cudaGetSymbolAddress((void**)&p_ctx,   g_ctx);
    cudaGetSymbolAddress((void**)&p_Ah,    g_Ah);
    cudaGetSymbolAddress((void**)&p_Al,    g_Al);
    cudaGetSymbolAddress((void**)&p_Wh,    g_Wh);
    cudaGetSymbolAddress((void**)&p_Wl,    g_Wl);
    cudaGetSymbolAddress((void**)&p_xh,    g_xh);
    cudaGetSymbolAddress((void**)&p_xl,    g_xl);
    cudaGetSymbolAddress((void**)&p_wih_h, g_wih_h);
    cudaGetSymbolAddress((void**)&p_wih_l, g_wih_l);
    cudaGetSymbolAddress((void**)&p_bar,   g_bar);

    const int PERSIST_SMEM = (4*4*HH + HH*BB + 1536) * sizeof(float);  // ~104 KB
    cudaFuncSetAttribute(lstm_persist, cudaFuncAttributeMaxDynamicSharedMemorySize, PERSIST_SMEM);
    cudaFuncSetAttribute(gemm_logits_mma, cudaFuncAttributeMaxDynamicSharedMemorySize, GSMEM);
    cudaFuncSetAttribute(gemm_xw_mma, cudaFuncAttributeMaxDynamicSharedMemorySize, GSMEM);

    init_state<<<64, 256>>>(hidden, cell, p_h0, p_h1, p_c0, p_c1, p_bar);
    gather_emb<<<MROWS, 128>>>(tgt, emb, p_x);
    conv_flat<<<(int)(((size_t)VV*KTOT)/8/256), 256>>>(W2, p_Wh, p_Wl);

    // layer 0
    conv_flat<<<512, 256>>>(p_x, p_xh, p_xl);
    conv_flat<<<512, 256>>>(Wih0, p_wih_h, p_wih_l);
    gemm_xw_mma<<<dim3(16, 16), 256, GSMEM>>>(p_xh, p_xl, p_wih_h, p_wih_l, p_xw, bih0, bhh0);
    lstm_persist<<<128, 512, PERSIST_SMEM>>>(p_xw, Whh0, p_h0, p_c0, p_ys0, p_bar);

    // layer 1
    conv_flat<<<512, 256>>>(p_ys0, p_xh, p_xl);
    conv_flat<<<512, 256>>>(Wih1, p_wih_h, p_wih_l);
    gemm_xw_mma<<<dim3(16, 16), 256, GSMEM>>>(p_xh, p_xl, p_wih_h, p_wih_l, p_xw, bih1, bhh1);
    lstm_persist<<<128, 512, PERSIST_SMEM>>>(p_xw, Whh1, p_h1, p_c1, p_ys1, p_bar + TT);

    ctx_kernel<<<BB, HH>>>(enc, srcmask, p_ctx);
    conv_a<<<MROWS, 128>>>(p_ys1, p_ctx, p_Ah, p_Al);
    gemm_logits_mma<<<dim3(MROWS/128, VV/128), 256, GSMEM>>>(p_Ah, p_Al, p_Wh, p_Wl, out);

    tail_kernel<<<64, 1024>>>(p_ys0, p_ys1, p_c0, p_c1, out);
}

// round 14
// speedup vs baseline: 2.4326x; 1.3963x over previous
#include <cuda_runtime.h>
#include <cuda_bf16.h>
#include <cuda_fp16.h>
#include <math.h>
#include <stdint.h>

#define TT 64
#define BB 32
#define HH 512
#define VV 32000
#define SS 64
#define MROWS (TT*BB)      // 2048
#define G4H (4*HH)         // 2048
#define KTOT 1024

// ---- static scratch ----
__device__ float g_x   [MROWS*HH];
__device__ float g_xw  [MROWS*G4H];          // input proj, transposed [gate_row][m]
__device__ float g_ys0 [MROWS*HH];
__device__ float g_ys1 [MROWS*HH];
__device__ float g_h0  [2][HH*BB];
__device__ float g_h1  [2][HH*BB];
__device__ float g_c0  [HH*BB];
__device__ float g_c1  [HH*BB];
__device__ float g_ctx [BB*HH];
__device__ int   g_bar [2*TT];
__device__ __half g_Ah[MROWS*KTOT];          // [dec|ctx] fp16 (single plane)
__device__ __half g_Wh[(size_t)VV*KTOT];     // W2 fp16 (single plane)
__device__ __nv_bfloat16 g_xh[MROWS*HH];     // x / ys0 split hi (bf16, xw gemm)
__device__ __nv_bfloat16 g_xl[MROWS*HH];
__device__ __nv_bfloat16 g_wih_h[G4H*HH];
__device__ __nv_bfloat16 g_wih_l[G4H*HH];

extern __shared__ char dynsmem[];

#define SWZ(o) ((o) ^ (((o) >> 3) & 0x70))

__device__ __forceinline__ uint32_t s2u(const void* p) {
    uint32_t a;
    asm("{ .reg .u64 t; cvta.to.shared.u64 t, %1; cvt.u32.u64 %0, t; }" : "=r"(a) : "l"(p));
    return a;
}
__device__ __forceinline__ void cp16(uint32_t smem, const void* g) {
    asm volatile("cp.async.cg.shared.global [%0], [%1], 16;" :: "r"(smem), "l"(g));
}
#define CP_COMMIT() asm volatile("cp.async.commit_group;" ::: "memory")
#define CP_WAIT1()  asm volatile("cp.async.wait_group 1;" ::: "memory")
#define CP_WAIT0()  asm volatile("cp.async.wait_group 0;" ::: "memory")

__device__ __forceinline__ void ldsm4(uint32_t* r, uint32_t addr) {
    asm volatile("ldmatrix.sync.aligned.m8n8.x4.shared.b16 {%0,%1,%2,%3}, [%4];"
        : "=r"(r[0]), "=r"(r[1]), "=r"(r[2]), "=r"(r[3]) : "r"(addr));
}
__device__ __forceinline__ void mma16816_bf(float* d, const uint32_t* a, const uint32_t* b) {
    asm volatile(
        "mma.sync.aligned.m16n8k16.row.col.f32.bf16.bf16.f32 "
        "{%0,%1,%2,%3}, {%4,%5,%6,%7}, {%8,%9}, {%0,%1,%2,%3};"
        : "+f"(d[0]), "+f"(d[1]), "+f"(d[2]), "+f"(d[3])
        : "r"(a[0]), "r"(a[1]), "r"(a[2]), "r"(a[3]), "r"(b[0]), "r"(b[1]));
}
__device__ __forceinline__ void mma16816_fp(float* d, const uint32_t* a, const uint32_t* b) {
    asm volatile(
        "mma.sync.aligned.m16n8k16.row.col.f32.f16.f16.f32 "
        "{%0,%1,%2,%3}, {%4,%5,%6,%7}, {%8,%9}, {%0,%1,%2,%3};"
        : "+f"(d[0]), "+f"(d[1]), "+f"(d[2]), "+f"(d[3])
        : "r"(a[0]), "r"(a[1]), "r"(a[2]), "r"(a[3]), "r"(b[0]), "r"(b[1]));
}

// ---- init / gather ----
__global__ void init_state(const float* __restrict__ hidden, const float* __restrict__ cell,
                           float* h0, float* h1, float* c0, float* c1, int* bar) {
    int idx = blockIdx.x * blockDim.x + threadIdx.x;
    if (idx < 2*TT) bar[idx] = 0;
    if (idx >= HH*BB) return;
    int j = idx >> 5, b = idx & 31;
    int src = b * HH + j;
    h0[idx] = hidden[src];  h1[idx] = hidden[HH*BB + src];
    c0[idx] = cell[src];    c1[idx] = cell[HH*BB + src];
}
__global__ void gather_emb(const int* __restrict__ tgt, const float* __restrict__ emb,
                           float* __restrict__ x) {
    int m = blockIdx.x, r = tgt[m];
    reinterpret_cast<float4*>(x + (size_t)m * HH)[threadIdx.x] =
        reinterpret_cast<const float4*>(emb + (size_t)r * HH)[threadIdx.x];
}

// ---- fp32 -> bf16 hi/lo split (for xw GEMM) ----
__device__ __forceinline__ void split8(const float* src, __nv_bfloat16* hi, __nv_bfloat16* lo) {
    float4 f0 = *reinterpret_cast<const float4*>(src);
    float4 f1 = *reinterpret_cast<const float4*>(src + 4);
    float fv[8] = {f0.x,f0.y,f0.z,f0.w,f1.x,f1.y,f1.z,f1.w};
    __nv_bfloat16 h8[8], l8[8];
    #pragma unroll
    for (int q = 0; q < 8; q++) {
        h8[q] = __float2bfloat16_rn(fv[q]);
        l8[q] = __float2bfloat16_rn(fv[q] - __bfloat162float(h8[q]));
    }
    *reinterpret_cast<uint4*>(hi) = *reinterpret_cast<uint4*>(h8);
    *reinterpret_cast<uint4*>(lo) = *reinterpret_cast<uint4*>(l8);
}
__global__ void conv_flat(const float* __restrict__ src, __nv_bfloat16* hi, __nv_bfloat16* lo) {
    size_t i = ((size_t)blockIdx.x * blockDim.x + threadIdx.x) * 8;
    split8(src + i, hi + i, lo + i);
}

// ---- fp32 -> fp16 single-plane converters (for logits GEMM) ----
__device__ __forceinline__ void cvt8h(const float* src, __half* dst) {
    float4 f0 = *reinterpret_cast<const float4*>(src);
    float4 f1 = *reinterpret_cast<const float4*>(src + 4);
    float fv[8] = {f0.x,f0.y,f0.z,f0.w,f1.x,f1.y,f1.z,f1.w};
    __half h8[8];
    #pragma unroll
    for (int q = 0; q < 8; q++) h8[q] = __float2half_rn(fv[q]);
    *reinterpret_cast<uint4*>(dst) = *reinterpret_cast<uint4*>(h8);
}
__global__ void conv_w_h(const float* __restrict__ W2, __half* __restrict__ dst) {
    size_t i = ((size_t)blockIdx.x * blockDim.x + threadIdx.x) * 8;
    cvt8h(W2 + i, dst + i);
}
__global__ void conv_a_h(const float* __restrict__ dec, const float* __restrict__ ctx,
                         __half* __restrict__ dst) {
    int m = blockIdx.x, t8 = threadIdx.x * 8;
    const float* src = (t8 < HH) ? dec + (size_t)m*HH + t8
                                 : ctx + (size_t)(m & 31)*HH + (t8 - HH);
    cvt8h(src, dst + (size_t)m * KTOT + t8);
}

// ---- mma input-projection GEMM (bf16 3-pass, validated) --------------------
#define PLANE 16384
#define BUFSTR4 (4*PLANE)
#define GSMEM_XW (2*BUFSTR4)     // 128 KB

__global__ __launch_bounds__(256, 1)
void gemm_xw_mma(const __nv_bfloat16* __restrict__ Ah, const __nv_bfloat16* __restrict__ Al,
                 const __nv_bfloat16* __restrict__ Bh, const __nv_bfloat16* __restrict__ Bl,
                 float* __restrict__ C,
                 const float* __restrict__ bias0, const float* __restrict__ bias1) {
    uint32_t sb = s2u(dynsmem);
    int tid = threadIdx.x, wid = tid >> 5, lane = tid & 31;
    int bm = blockIdx.x * 128, bn = blockIdx.y * 128;
    int wm = (wid & 3) * 32, wn = (wid >> 2) * 64;

    float acc[2][8][4];
    #pragma unroll
    for (int mt = 0; mt < 2; mt++)
        #pragma unroll
        for (int nt = 0; nt < 8; nt++)
            #pragma unroll
            for (int q = 0; q < 4; q++) acc[mt][nt][q] = 0.f;

    const __nv_bfloat16* gsrc[4] = {Ah, Al, Bh, Bl};
    auto fill = [&](int c, int buf) {
        uint32_t base = sb + buf * BUFSTR4;
        #pragma unroll
        for (int it = 0; it < 16; it++) {
            int i = tid + it * 256;
            int p = i >> 10, j = i & 1023;
            int r = j >> 3, seg = j & 7;
            int grow = (p < 2) ? (bm + r) : (bn + r);
            const __nv_bfloat16* g = gsrc[p] + ((size_t)grow << 9) + (c << 6) + (seg << 3);
            cp16(base + p * PLANE + SWZ((uint32_t)(r * 128 + seg * 16)), g);
        }
        CP_COMMIT();
    };

    fill(0, 0);
    for (int c = 0; c < 8; c++) {
        int buf = c & 1;
        if (c + 1 < 8) { fill(c + 1, buf ^ 1); CP_WAIT1(); }
        else           { CP_WAIT0(); }
        __syncthreads();
        uint32_t base = sb + buf * BUFSTR4;
        #pragma unroll
        for (int kk = 0; kk < 4; kk++) {
            uint32_t afh[2][4], afl[2][4];
            #pragma unroll
            for (int mt = 0; mt < 2; mt++) {
                int r = wm + mt * 16 + (lane & 15);
                uint32_t off = SWZ((uint32_t)(r * 128 + kk * 32 + (lane >> 4) * 16));
                ldsm4(afh[mt], base + 0 * PLANE + off);
                ldsm4(afl[mt], base + 1 * PLANE + off);
            }
            uint32_t bfh[4][4], bfl[4][4];
            #pragma unroll
            for (int np = 0; np < 4; np++) {
                int nrow = wn + np * 16 + (lane & 7) + ((lane >> 4) << 3);
                uint32_t off = SWZ((uint32_t)(nrow * 128 + kk * 32 + ((lane >> 3) & 1) * 16));
                ldsm4(bfh[np], base + 2 * PLANE + off);
                ldsm4(bfl[np], base + 3 * PLANE + off);
            }
            #pragma unroll
            for (int mt = 0; mt < 2; mt++)
                #pragma unroll
                for (int nt = 0; nt < 8; nt++) {
                    const uint32_t* bh = &bfh[nt >> 1][(nt & 1) * 2];
                    const uint32_t* bl = &bfl[nt >> 1][(nt & 1) * 2];
                    mma16816_bf(acc[mt][nt], afh[mt], bh);
                    mma16816_bf(acc[mt][nt], afh[mt], bl);
                    mma16816_bf(acc[mt][nt], afl[mt], bh);
                }
        }
        __syncthreads();
    }
    #pragma unroll
    for (int mt = 0; mt < 2; mt++) {
        int r0 = bm + wm + mt * 16 + (lane >> 2);
        #pragma unroll
        for (int nt = 0; nt < 8; nt++) {
            int n0 = bn + wn + nt * 8 + (lane & 3) * 2;
            float b0 = bias0[n0] + bias1[n0];
            float b1 = bias0[n0+1] + bias1[n0+1];
            C[(size_t)n0     * MROWS + r0]     = acc[mt][nt][0] + b0;
            C[(size_t)(n0+1) * MROWS + r0]     = acc[mt][nt][1] + b1;
            C[(size_t)n0     * MROWS + r0 + 8] = acc[mt][nt][2] + b0;
            C[(size_t)(n0+1) * MROWS + r0 + 8] = acc[mt][nt][3] + b1;
        }
    }
}

// ---- persistent LSTM: split-K x4 (512 threads), tight-poll barrier ----------
__device__ __forceinline__ float sigmoidf_(float x) { return 1.f / (1.f + expf(-x)); }

__global__ __launch_bounds__(512)
void lstm_persist(const float* __restrict__ xwT, const float* __restrict__ W_hh,
                  float* __restrict__ hbuf, float* __restrict__ cbuf,
                  float* __restrict__ ys, int* __restrict__ bar) {
    float* smemf = reinterpret_cast<float*>(dynsmem);
    float* Ws = smemf;                 // 16 x 512
    float* Hs = smemf + 4*4*HH;        // 512 x 32
    float* Ps = Hs + HH*BB;            // partials [3][4][4][32]

    int tid = threadIdx.x, w = tid >> 5, b = tid & 31, cta = blockIdx.x;
    int q = w >> 2, jl = w & 3;
    int jg = cta * 4 + jl;

    #pragma unroll
    for (int it = 0; it < 4; it++) {
        int idx = tid + it * 512;
        int row = idx >> 7, col4 = idx & 127;
        int g = row >> 2, j2 = row & 3;
        reinterpret_cast<float4*>(Ws)[row * 128 + col4] =
            reinterpret_cast<const float4*>(W_hh + (size_t)(g*HH + cta*4 + j2) * HH)[col4];
    }
    float creg = (q == 0) ? cbuf[jg*32 + b] : 0.f;
    __syncthreads();

    const float4* wi = reinterpret_cast<const float4*>(&Ws[(0*4 + jl) * HH]) + q*32;
    const float4* wf = reinterpret_cast<const float4*>(&Ws[(1*4 + jl) * HH]) + q*32;
    const float4* wg = reinterpret_cast<const float4*>(&Ws[(2*4 + jl) * HH]) + q*32;
    const float4* wo = reinterpret_cast<const float4*>(&Ws[(3*4 + jl) * HH]) + q*32;
    const float* Hh = Hs + q * 128 * 32;

    volatile int* vbar = (volatile int*)bar;

    for (int t = 0; t < TT; t++) {
        int m = t*32 + b;
        // gate-bias loads first: independent of h -> overlap with staging
        float ai0 = 0.f, af0 = 0.f, ag0 = 0.f, ao0 = 0.f;
        float ai1 = 0.f, af1 = 0.f, ag1 = 0.f, ao1 = 0.f;
        if (q == 0) {
            ai0 = xwT[(size_t)(0*HH + jg) * MROWS + m];
            af0 = xwT[(size_t)(1*HH + jg) * MROWS + m];
            ag0 = xwT[(size_t)(2*HH + jg) * MROWS + m];
            ao0 = xwT[(size_t)(3*HH + jg) * MROWS + m];
        }
        {   // stage h(t): 4096 float4 over 512 threads
            const float4* hsrc = reinterpret_cast<const float4*>(hbuf + (t & 1) * HH*BB);
            float4* hdst = reinterpret_cast<float4*>(Hs);
            #pragma unroll
            for (int i = 0; i < 8; i++)
                hdst[tid + (i << 9)] = __ldcg(hsrc + tid + (i << 9));
        }
        __syncthreads();

        #pragma unroll 8
        for (int k4 = 0; k4 < 32; k4 += 2) {
            {
                float4 vi = wi[k4], vf = wf[k4], vg = wg[k4], vo = wo[k4];
                int k = k4 << 2;
                float h0 = Hh[(k+0)*32 + b], h1 = Hh[(k+1)*32 + b];
                float h2 = Hh[(k+2)*32 + b], h3 = Hh[(k+3)*32 + b];
                ai0 = fmaf(vi.x,h0,ai0); af0 = fmaf(vf.x,h0,af0); ag0 = fmaf(vg.x,h0,ag0); ao0 = fmaf(vo.x,h0,ao0);
                ai0 = fmaf(vi.y,h1,ai0); af0 = fmaf(vf.y,h1,af0); ag0 = fmaf(vg.y,h1,ag0); ao0 = fmaf(vo.y,h1,ao0);
                ai0 = fmaf(vi.z,h2,ai0); af0 = fmaf(vf.z,h2,af0); ag0 = fmaf(vg.z,h2,ag0); ao0 = fmaf(vo.z,h2,ao0);
                ai0 = fmaf(vi.w,h3,ai0); af0 = fmaf(vf.w,h3,af0); ag0 = fmaf(vg.w,h3,ag0); ao0 = fmaf(vo.w,h3,ao0);
            }
            {
                float4 vi = wi[k4+1], vf = wf[k4+1], vg = wg[k4+1], vo = wo[k4+1];
                int k = (k4+1) << 2;
                float h0 = Hh[(k+0)*32 + b], h1 = Hh[(k+1)*32 + b];
                float h2 = Hh[(k+2)*32 + b], h3 = Hh[(k+3)*32 + b];
                ai1 = fmaf(vi.x,h0,ai1); af1 = fmaf(vf.x,h0,af1); ag1 = fmaf(vg.x,h0,ag1); ao1 = fmaf(vo.x,h0,ao1);
                ai1 = fmaf(vi.y,h1,ai1); af1 = fmaf(vf.y,h1,af1); ag1 = fmaf(vg.y,h1,ag1); ao1 = fmaf(vo.y,h1,ao1);
                ai1 = fmaf(vi.z,h2,ai1); af1 = fmaf(vf.z,h2,af1); ag1 = fmaf(vg.z,h2,ag1); ao1 = fmaf(vo.z,h2,ao1);
                ai1 = fmaf(vi.w,h3,ai1); af1 = fmaf(vf.w,h3,af1); ag1 = fmaf(vg.w,h3,ag1); ao1 = fmaf(vo.w,h3,ao1);
            }
        }
        float ai = ai0 + ai1, af = af0 + af1, ag = ag0 + ag1, ao = ao0 + ao1;

        if (q != 0) {
            int o = jl*32 + b;
            Ps[(q-1)*512 + 0*128 + o] = ai;
            Ps[(q-1)*512 + 1*128 + o] = af;
            Ps[(q-1)*512 + 2*128 + o] = ag;
            Ps[(q-1)*512 + 3*128 + o] = ao;
        }
        __syncthreads();
        if (q == 0) {
            int o = jl*32 + b;
            ai += Ps[0*512 + 0*128 + o] + Ps[1*512 + 0*128 + o] + Ps[2*512 + 0*128 + o];
            af += Ps[0*512 + 1*128 + o] + Ps[1*512 + 1*128 + o] + Ps[2*512 + 1*128 + o];
            ag += Ps[0*512 + 2*128 + o] + Ps[1*512 + 2*128 + o] + Ps[2*512 + 2*128 + o];
            ao += Ps[0*512 + 3*128 + o] + Ps[1*512 + 3*128 + o] + Ps[2*512 + 3*128 + o];
            float ig = sigmoidf_(ai), fg = sigmoidf_(af);
            float gg = tanhf(ag),    og = sigmoidf_(ao);
            float c_new = fmaf(fg, creg, ig * gg);
            float h_new = og * tanhf(c_new);
            creg = c_new;
            hbuf[((t+1)&1) * HH*BB + jg*32 + b] = h_new;
            ys[(size_t)m * HH + jg] = h_new;
            if (t == TT-1) cbuf[jg*32 + b] = creg;
            __threadfence();
        }
        __syncthreads();
        if (tid == 0) {
            atomicAdd(&bar[t], 1);
            while (vbar[t] < (int)gridDim.x) { }
            __threadfence();
        }
        __syncthreads();
    }
}

// ---- ctx: exact softmax shortcut = masked mean over S ----
__global__ void ctx_kernel(const float* __restrict__ enc, const int* __restrict__ src_mask,
                           float* __restrict__ ctx) {
    int b = blockIdx.x, h = threadIdx.x;
    float s_un = 0.f, s_all = 0.f; int cnt = 0;
    #pragma unroll 4
    for (int s = 0; s < SS; s++) {
        float v = enc[((size_t)s * BB + b) * HH + h];
        s_all += v;
        if (src_mask[s * BB + b] == 0) { s_un += v; cnt++; }
    }
    ctx[b * HH + h] = (cnt > 0) ? (s_un / (float)cnt) : (s_all / (float)SS);
}

// ---- fp16 single-pass logits GEMM: out[2048,32000] = Acat @ W2cat^T --------
// err ~2e-4 (norm): per-side fp16 rounding 2^-12 rms. 2 planes, double buffer.
#define CHUNKS 16
#define BUFSTR2 (2*PLANE)
#define GSMEM_LG (2*BUFSTR2)     // 64 KB

__global__ __launch_bounds__(256, 1)
void gemm_logits_mma(const __half* __restrict__ Ah, const __half* __restrict__ Bh,
                     float* __restrict__ out) {
    uint32_t sb = s2u(dynsmem);
    int tid = threadIdx.x, wid = tid >> 5, lane = tid & 31;
    int bm = blockIdx.x * 128, bn = blockIdx.y * 128;
    int wm = (wid & 3) * 32, wn = (wid >> 2) * 64;

    float acc[2][8][4];
    #pragma unroll
    for (int mt = 0; mt < 2; mt++)
        #pragma unroll
        for (int nt = 0; nt < 8; nt++)
            #pragma unroll
            for (int q = 0; q < 4; q++) acc[mt][nt][q] = 0.f;

    const __half* gsrc[2] = {Ah, Bh};
    auto fill = [&](int c, int buf) {
        uint32_t base = sb + buf * BUFSTR2;
        #pragma unroll
        for (int it = 0; it < 8; it++) {
            int i = tid + it * 256;
            int p = i >> 10, j = i & 1023;
            int r = j >> 3, seg = j & 7;
            int grow = (p == 0) ? (bm + r) : (bn + r);
            const __half* g = gsrc[p] + ((size_t)grow << 10) + (c << 6) + (seg << 3);
            cp16(base + p * PLANE + SWZ((uint32_t)(r * 128 + seg * 16)), g);
        }
        CP_COMMIT();
    };

    fill(0, 0);
    for (int c = 0; c < CHUNKS; c++) {
        int buf = c & 1;
        if (c + 1 < CHUNKS) { fill(c + 1, buf ^ 1); CP_WAIT1(); }
        else                { CP_WAIT0(); }
        __syncthreads();
        uint32_t base = sb + buf * BUFSTR2;
        #pragma unroll
        for (int kk = 0; kk < 4; kk++) {
            uint32_t af[2][4];
            #pragma unroll
            for (int mt = 0; mt < 2; mt++) {
                int r = wm + mt * 16 + (lane & 15);
                uint32_t off = SWZ((uint32_t)(r * 128 + kk * 32 + (lane >> 4) * 16));
                ldsm4(af[mt], base + 0 * PLANE + off);
            }
            uint32_t bf[4][4];
            #pragma unroll
            for (int np = 0; np < 4; np++) {
                int nrow = wn + np * 16 + (lane & 7) + ((lane >> 4) << 3);
                uint32_t off = SWZ((uint32_t)(nrow * 128 + kk * 32 + ((lane >> 3) & 1) * 16));
                ldsm4(bf[np], base + 1 * PLANE + off);
            }
            #pragma unroll
            for (int mt = 0; mt < 2; mt++)
                #pragma unroll
                for (int nt = 0; nt < 8; nt++)
                    mma16816_fp(acc[mt][nt], af[mt], &bf[nt >> 1][(nt & 1) * 2]);
        }
        __syncthreads();
    }
    #pragma unroll
    for (int mt = 0; mt < 2; mt++) {
        int r0 = bm + wm + mt * 16 + (lane >> 2);
        #pragma unroll
        for (int nt = 0; nt < 8; nt++) {
            int cidx = bn + wn + nt * 8 + (lane & 3) * 2;
            *reinterpret_cast<float2*>(out + (size_t)r0 * VV + cidx) =
                make_float2(acc[mt][nt][0], acc[mt][nt][1]);
            *reinterpret_cast<float2*>(out + (size_t)(r0 + 8) * VV + cidx) =
                make_float2(acc[mt][nt][2], acc[mt][nt][3]);
        }
    }
}

// ---- tail: hs / cs ----
__global__ void tail_kernel(const float* __restrict__ ys0, const float* __restrict__ ys1,
                            const float* __restrict__ c0, const float* __restrict__ c1,
                            float* __restrict__ out) {
    int idx = blockIdx.x * blockDim.x + threadIdx.x;
    if (idx >= 4*HH*BB) return;
    int seg = idx >> 14, i = idx & 16383;
    int b = i >> 9, j = i & 511;
    float v;
    if      (seg == 0) v = ys0[((size_t)(TT-1)*BB + b) * HH + j];
    else if (seg == 1) v = ys1[((size_t)(TT-1)*BB + b) * HH + j];
    else if (seg == 2) v = c0[j*32 + b];
    else               v = c1[j*32 + b];
    out[(size_t)MROWS * VV + idx] = v;
}

// ---- launch ----
extern "C" void kernel_launch(void* const* d_in, const int* in_sizes, int n_in,
                              void* d_out, int out_size) {
    (void)in_sizes; (void)n_in; (void)out_size;
    const int*   tgt     = (const int*)  d_in[0];
    const float* hidden  = (const float*)d_in[1];
    const float* cell    = (const float*)d_in[2];
    const float* enc     = (const float*)d_in[3];
    const int*   srcmask = (const int*)  d_in[4];
    const float* emb     = (const float*)d_in[5];
    const float* Wih0    = (const float*)d_in[6];
    const float* Whh0    = (const float*)d_in[7];
    const float* bih0    = (const float*)d_in[8];
    const float* bhh0    = (const float*)d_in[9];
    const float* Wih1    = (const float*)d_in[10];
    const float* Whh1    = (const float*)d_in[11];
    const float* bih1    = (const float*)d_in[12];
    const float* bhh1    = (const float*)d_in[13];
    // d_in[14] = W1: provably irrelevant (softmax shortcut)
    const float* W2      = (const float*)d_in[15];
    float* out = (float*)d_out;

    float *p_x, *p_xw, *p_ys0, *p_ys1, *p_h0, *p_h1, *p_c0, *p_c1, *p_ctx;
    __half *p_Ah, *p_Wh;
    __nv_bfloat16 *p_xh, *p_xl, *p_wih_h, *p_wih_l;
    int *p_bar;
    cudaGetSymbolAddress((void**)&p_x,     g_x);
    cudaGetSymbolAddress((void**)&p_xw,    g_xw);
    cudaGetSymbolAddress((void**)&p_ys0,   g_ys0);
    cudaGetSymbolAddress((void**)&p_ys1,   g_ys1);
    cudaGetSymbolAddress((void**)&p_h0,    g_h0);
    cudaGetSymbolAddress((void**)&p_h1,    g_h1);
    cudaGetSymbolAddress((void**)&p_c0,    g_c0);
    cudaGetSymbolAddress((void**)&p_c1,    g_c1);
    cudaGetSymbolAddress((void**)&p_ctx,   g_ctx);
    cudaGetSymbolAddress((void**)&p_Ah,    g_Ah);
    cudaGetSymbolAddress((void**)&p_Wh,    g_Wh);
    cudaGetSymbolAddress((void**)&p_xh,    g_xh);
    cudaGetSymbolAddress((void**)&p_xl,    g_xl);
    cudaGetSymbolAddress((void**)&p_wih_h, g_wih_h);
    cudaGetSymbolAddress((void**)&p_wih_l, g_wih_l);
    cudaGetSymbolAddress((void**)&p_bar,   g_bar);

    const int PERSIST_SMEM = (4*4*HH + HH*BB + 1536) * sizeof(float);  // ~104 KB
    cudaFuncSetAttribute(lstm_persist, cudaFuncAttributeMaxDynamicSharedMemorySize, PERSIST_SMEM);
    cudaFuncSetAttribute(gemm_logits_mma, cudaFuncAttributeMaxDynamicSharedMemorySize, GSMEM_LG);
    cudaFuncSetAttribute(gemm_xw_mma, cudaFuncAttributeMaxDynamicSharedMemorySize, GSMEM_XW);

    init_state<<<64, 256>>>(hidden, cell, p_h0, p_h1, p_c0, p_c1, p_bar);
    gather_emb<<<MROWS, 128>>>(tgt, emb, p_x);
    conv_w_h<<<(int)(((size_t)VV*KTOT)/8/256), 256>>>(W2, p_Wh);

    // layer 0
    conv_flat<<<512, 256>>>(p_x, p_xh, p_xl);
    conv_flat<<<512, 256>>>(Wih0, p_wih_h, p_wih_l);
    gemm_xw_mma<<<dim3(16, 16), 256, GSMEM_XW>>>(p_xh, p_xl, p_wih_h, p_wih_l, p_xw, bih0, bhh0);
    lstm_persist<<<128, 512, PERSIST_SMEM>>>(p_xw, Whh0, p_h0, p_c0, p_ys0, p_bar);

    // layer 1
    conv_flat<<<512, 256>>>(p_ys0, p_xh, p_xl);
    conv_flat<<<512, 256>>>(Wih1, p_wih_h, p_wih_l);
    gemm_xw_mma<<<dim3(16, 16), 256, GSMEM_XW>>>(p_xh, p_xl, p_wih_h, p_wih_l, p_xw, bih1, bhh1);
    lstm_persist<<<128, 512, PERSIST_SMEM>>>(p_xw, Whh1, p_h1, p_c1, p_ys1, p_bar + TT);

    ctx_kernel<<<BB, HH>>>(enc, srcmask, p_ctx);
    conv_a_h<<<MROWS, 128>>>(p_ys1, p_ctx, p_Ah);
    gemm_logits_mma<<<dim3(MROWS/128, VV/128), 256, GSMEM_LG>>>(p_Ah, p_Wh, out);

    tail_kernel<<<64, 1024>>>(p_ys0, p_ys1, p_c0, p_c1, out);
}

// round 15
// speedup vs baseline: 2.4328x; 1.0001x over previous
#include <cuda_runtime.h>
#include <cuda_bf16.h>
#include <cuda_fp16.h>
#include <math.h>
#include <stdint.h>

#define TT 64
#define BB 32
#define HH 512
#define VV 32000
#define SS 64
#define MROWS (TT*BB)      // 2048
#define G4H (4*HH)         // 2048
#define KTOT 1024

// ---- static scratch ----
__device__ float g_x   [MROWS*HH];
__device__ float g_xw  [MROWS*G4H];          // input proj, transposed [gate_row][m]
__device__ float g_ys0 [MROWS*HH];
__device__ float g_ys1 [MROWS*HH];
__device__ float g_h0  [2][HH*BB];
__device__ float g_h1  [2][HH*BB];
__device__ float g_c0  [HH*BB];
__device__ float g_c1  [HH*BB];
__device__ float g_ctx [BB*HH];
__device__ int   g_bar [2*TT];
__device__ __half g_Ah[MROWS*KTOT];          // [dec|ctx] fp16 (single plane)
__device__ __half g_Wh[(size_t)VV*KTOT];     // W2 fp16 (single plane)
__device__ __nv_bfloat16 g_xh[MROWS*HH];     // x / ys0 split hi (bf16, xw gemm)
__device__ __nv_bfloat16 g_xl[MROWS*HH];
__device__ __nv_bfloat16 g_wih_h[G4H*HH];
__device__ __nv_bfloat16 g_wih_l[G4H*HH];

extern __shared__ char dynsmem[];

#define SWZ(o) ((o) ^ (((o) >> 3) & 0x70))

__device__ __forceinline__ uint32_t s2u(const void* p) {
    uint32_t a;
    asm("{ .reg .u64 t; cvta.to.shared.u64 t, %1; cvt.u32.u64 %0, t; }" : "=r"(a) : "l"(p));
    return a;
}
__device__ __forceinline__ void cp16(uint32_t smem, const void* g) {
    asm volatile("cp.async.cg.shared.global [%0], [%1], 16;" :: "r"(smem), "l"(g));
}
#define CP_COMMIT() asm volatile("cp.async.commit_group;" ::: "memory")
#define CP_WAIT1()  asm volatile("cp.async.wait_group 1;" ::: "memory")
#define CP_WAIT0()  asm volatile("cp.async.wait_group 0;" ::: "memory")

__device__ __forceinline__ void ldsm4(uint32_t* r, uint32_t addr) {
    asm volatile("ldmatrix.sync.aligned.m8n8.x4.shared.b16 {%0,%1,%2,%3}, [%4];"
        : "=r"(r[0]), "=r"(r[1]), "=r"(r[2]), "=r"(r[3]) : "r"(addr));
}
__device__ __forceinline__ void mma16816_bf(float* d, const uint32_t* a, const uint32_t* b) {
    asm volatile(
        "mma.sync.aligned.m16n8k16.row.col.f32.bf16.bf16.f32 "
        "{%0,%1,%2,%3}, {%4,%5,%6,%7}, {%8,%9}, {%0,%1,%2,%3};"
        : "+f"(d[0]), "+f"(d[1]), "+f"(d[2]), "+f"(d[3])
        : "r"(a[0]), "r"(a[1]), "r"(a[2]), "r"(a[3]), "r"(b[0]), "r"(b[1]));
}
__device__ __forceinline__ void mma16816_fp(float* d, const uint32_t* a, const uint32_t* b) {
    asm volatile(
        "mma.sync.aligned.m16n8k16.row.col.f32.f16.f16.f32 "
        "{%0,%1,%2,%3}, {%4,%5,%6,%7}, {%8,%9}, {%0,%1,%2,%3};"
        : "+f"(d[0]), "+f"(d[1]), "+f"(d[2]), "+f"(d[3])
        : "r"(a[0]), "r"(a[1]), "r"(a[2]), "r"(a[3]), "r"(b[0]), "r"(b[1]));
}

// ---- init / gather ----
__global__ void init_state(const float* __restrict__ hidden, const float* __restrict__ cell,
                           float* h0, float* h1, float* c0, float* c1, int* bar) {
    int idx = blockIdx.x * blockDim.x + threadIdx.x;
    if (idx < 2*TT) bar[idx] = 0;
    if (idx >= HH*BB) return;
    int j = idx >> 5, b = idx & 31;
    int src = b * HH + j;
    h0[idx] = hidden[src];  h1[idx] = hidden[HH*BB + src];
    c0[idx] = cell[src];    c1[idx] = cell[HH*BB + src];
}
__global__ void gather_emb(const int* __restrict__ tgt, const float* __restrict__ emb,
                           float* __restrict__ x) {
    int m = blockIdx.x, r = tgt[m];
    reinterpret_cast<float4*>(x + (size_t)m * HH)[threadIdx.x] =
        reinterpret_cast<const float4*>(emb + (size_t)r * HH)[threadIdx.x];
}

// ---- fp32 -> bf16 hi/lo split (for xw GEMM) ----
__device__ __forceinline__ void split8(const float* src, __nv_bfloat16* hi, __nv_bfloat16* lo) {
    float4 f0 = *reinterpret_cast<const float4*>(src);
    float4 f1 = *reinterpret_cast<const float4*>(src + 4);
    float fv[8] = {f0.x,f0.y,f0.z,f0.w,f1.x,f1.y,f1.z,f1.w};
    __nv_bfloat16 h8[8], l8[8];
    #pragma unroll
    for (int q = 0; q < 8; q++) {
        h8[q] = __float2bfloat16_rn(fv[q]);
        l8[q] = __float2bfloat16_rn(fv[q] - __bfloat162float(h8[q]));
    }
    *reinterpret_cast<uint4*>(hi) = *reinterpret_cast<uint4*>(h8);
    *reinterpret_cast<uint4*>(lo) = *reinterpret_cast<uint4*>(l8);
}
__global__ void conv_flat(const float* __restrict__ src, __nv_bfloat16* hi, __nv_bfloat16* lo) {
    size_t i = ((size_t)blockIdx.x * blockDim.x + threadIdx.x) * 8;
    split8(src + i, hi + i, lo + i);
}

// ---- fp32 -> fp16 single-plane converters (for logits GEMM) ----
__device__ __forceinline__ void cvt8h(const float* src, __half* dst) {
    float4 f0 = *reinterpret_cast<const float4*>(src);
    float4 f1 = *reinterpret_cast<const float4*>(src + 4);
    float fv[8] = {f0.x,f0.y,f0.z,f0.w,f1.x,f1.y,f1.z,f1.w};
    __half h8[8];
    #pragma unroll
    for (int q = 0; q < 8; q++) h8[q] = __float2half_rn(fv[q]);
    *reinterpret_cast<uint4*>(dst) = *reinterpret_cast<uint4*>(h8);
}
__global__ void conv_w_h(const float* __restrict__ W2, __half* __restrict__ dst) {
    size_t i = ((size_t)blockIdx.x * blockDim.x + threadIdx.x) * 8;
    cvt8h(W2 + i, dst + i);
}
__global__ void conv_a_h(const float* __restrict__ dec, const float* __restrict__ ctx,
                         __half* __restrict__ dst) {
    int m = blockIdx.x, t8 = threadIdx.x * 8;
    const float* src = (t8 < HH) ? dec + (size_t)m*HH + t8
                                 : ctx + (size_t)(m & 31)*HH + (t8 - HH);
    cvt8h(src, dst + (size_t)m * KTOT + t8);
}

// ---- mma input-projection GEMM (bf16 3-pass, validated) --------------------
#define PLANE 16384
#define BUFSTR4 (4*PLANE)
#define GSMEM_XW (2*BUFSTR4)     // 128 KB

__global__ __launch_bounds__(256, 1)
void gemm_xw_mma(const __nv_bfloat16* __restrict__ Ah, const __nv_bfloat16* __restrict__ Al,
                 const __nv_bfloat16* __restrict__ Bh, const __nv_bfloat16* __restrict__ Bl,
                 float* __restrict__ C,
                 const float* __restrict__ bias0, const float* __restrict__ bias1) {
    uint32_t sb = s2u(dynsmem);
    int tid = threadIdx.x, wid = tid >> 5, lane = tid & 31;
    int bm = blockIdx.x * 128, bn = blockIdx.y * 128;
    int wm = (wid & 3) * 32, wn = (wid >> 2) * 64;

    float acc[2][8][4];
    #pragma unroll
    for (int mt = 0; mt < 2; mt++)
        #pragma unroll
        for (int nt = 0; nt < 8; nt++)
            #pragma unroll
            for (int q = 0; q < 4; q++) acc[mt][nt][q] = 0.f;

    const __nv_bfloat16* gsrc[4] = {Ah, Al, Bh, Bl};
    auto fill = [&](int c, int buf) {
        uint32_t base = sb + buf * BUFSTR4;
        #pragma unroll
        for (int it = 0; it < 16; it++) {
            int i = tid + it * 256;
            int p = i >> 10, j = i & 1023;
            int r = j >> 3, seg = j & 7;
            int grow = (p < 2) ? (bm + r) : (bn + r);
            const __nv_bfloat16* g = gsrc[p] + ((size_t)grow << 9) + (c << 6) + (seg << 3);
            cp16(base + p * PLANE + SWZ((uint32_t)(r * 128 + seg * 16)), g);
        }
        CP_COMMIT();
    };

    fill(0, 0);
    for (int c = 0; c < 8; c++) {
        int buf = c & 1;
        if (c + 1 < 8) { fill(c + 1, buf ^ 1); CP_WAIT1(); }
        else           { CP_WAIT0(); }
        __syncthreads();
        uint32_t base = sb + buf * BUFSTR4;
        #pragma unroll
        for (int kk = 0; kk < 4; kk++) {
            uint32_t afh[2][4], afl[2][4];
            #pragma unroll
            for (int mt = 0; mt < 2; mt++) {
                int r = wm + mt * 16 + (lane & 15);
                uint32_t off = SWZ((uint32_t)(r * 128 + kk * 32 + (lane >> 4) * 16));
                ldsm4(afh[mt], base + 0 * PLANE + off);
                ldsm4(afl[mt], base + 1 * PLANE + off);
            }
            uint32_t bfh[4][4], bfl[4][4];
            #pragma unroll
            for (int np = 0; np < 4; np++) {
                int nrow = wn + np * 16 + (lane & 7) + ((lane >> 4) << 3);
                uint32_t off = SWZ((uint32_t)(nrow * 128 + kk * 32 + ((lane >> 3) & 1) * 16));
                ldsm4(bfh[np], base + 2 * PLANE + off);
                ldsm4(bfl[np], base + 3 * PLANE + off);
            }
            #pragma unroll
            for (int mt = 0; mt < 2; mt++)
                #pragma unroll
                for (int nt = 0; nt < 8; nt++) {
                    const uint32_t* bh = &bfh[nt >> 1][(nt & 1) * 2];
                    const uint32_t* bl = &bfl[nt >> 1][(nt & 1) * 2];
                    mma16816_bf(acc[mt][nt], afh[mt], bh);
                    mma16816_bf(acc[mt][nt], afh[mt], bl);
                    mma16816_bf(acc[mt][nt], afl[mt], bh);
                }
        }
        __syncthreads();
    }
    #pragma unroll
    for (int mt = 0; mt < 2; mt++) {
        int r0 = bm + wm + mt * 16 + (lane >> 2);
        #pragma unroll
        for (int nt = 0; nt < 8; nt++) {
            int n0 = bn + wn + nt * 8 + (lane & 3) * 2;
            float b0 = bias0[n0] + bias1[n0];
            float b1 = bias0[n0+1] + bias1[n0+1];
            C[(size_t)n0     * MROWS + r0]     = acc[mt][nt][0] + b0;
            C[(size_t)(n0+1) * MROWS + r0]     = acc[mt][nt][1] + b1;
            C[(size_t)n0     * MROWS + r0 + 8] = acc[mt][nt][2] + b0;
            C[(size_t)(n0+1) * MROWS + r0 + 8] = acc[mt][nt][3] + b1;
        }
    }
}

// ---- persistent LSTM: split-K x4 (512 threads), tight-poll barrier ----------
__device__ __forceinline__ float sigmoidf_(float x) { return 1.f / (1.f + expf(-x)); }

__global__ __launch_bounds__(512)
void lstm_persist(const float* __restrict__ xwT, const float* __restrict__ W_hh,
                  float* __restrict__ hbuf, float* __restrict__ cbuf,
                  float* __restrict__ ys, int* __restrict__ bar) {
    float* smemf = reinterpret_cast<float*>(dynsmem);
    float* Ws = smemf;                 // 16 x 512
    float* Hs = smemf + 4*4*HH;        // 512 x 32
    float* Ps = Hs + HH*BB;            // partials [3][4][4][32]

    int tid = threadIdx.x, w = tid >> 5, b = tid & 31, cta = blockIdx.x;
    int q = w >> 2, jl = w & 3;
    int jg = cta * 4 + jl;

    #pragma unroll
    for (int it = 0; it < 4; it++) {
        int idx = tid + it * 512;
        int row = idx >> 7, col4 = idx & 127;
        int g = row >> 2, j2 = row & 3;
        reinterpret_cast<float4*>(Ws)[row * 128 + col4] =
            reinterpret_cast<const float4*>(W_hh + (size_t)(g*HH + cta*4 + j2) * HH)[col4];
    }
    float creg = (q == 0) ? cbuf[jg*32 + b] : 0.f;
    __syncthreads();

    const float4* wi = reinterpret_cast<const float4*>(&Ws[(0*4 + jl) * HH]) + q*32;
    const float4* wf = reinterpret_cast<const float4*>(&Ws[(1*4 + jl) * HH]) + q*32;
    const float4* wg = reinterpret_cast<const float4*>(&Ws[(2*4 + jl) * HH]) + q*32;
    const float4* wo = reinterpret_cast<const float4*>(&Ws[(3*4 + jl) * HH]) + q*32;
    const float* Hh = Hs + q * 128 * 32;

    volatile int* vbar = (volatile int*)bar;

    for (int t = 0; t < TT; t++) {
        int m = t*32 + b;
        // gate-bias loads first: independent of h -> overlap with staging
        float ai0 = 0.f, af0 = 0.f, ag0 = 0.f, ao0 = 0.f;
        float ai1 = 0.f, af1 = 0.f, ag1 = 0.f, ao1 = 0.f;
        if (q == 0) {
            ai0 = xwT[(size_t)(0*HH + jg) * MROWS + m];
            af0 = xwT[(size_t)(1*HH + jg) * MROWS + m];
            ag0 = xwT[(size_t)(2*HH + jg) * MROWS + m];
            ao0 = xwT[(size_t)(3*HH + jg) * MROWS + m];
        }
        {   // stage h(t): 4096 float4 over 512 threads
            const float4* hsrc = reinterpret_cast<const float4*>(hbuf + (t & 1) * HH*BB);
            float4* hdst = reinterpret_cast<float4*>(Hs);
            #pragma unroll
            for (int i = 0; i < 8; i++)
                hdst[tid + (i << 9)] = __ldcg(hsrc + tid + (i << 9));
        }
        __syncthreads();

        #pragma unroll 8
        for (int k4 = 0; k4 < 32; k4 += 2) {
            {
                float4 vi = wi[k4], vf = wf[k4], vg = wg[k4], vo = wo[k4];
                int k = k4 << 2;
                float h0 = Hh[(k+0)*32 + b], h1 = Hh[(k+1)*32 + b];
                float h2 = Hh[(k+2)*32 + b], h3 = Hh[(k+3)*32 + b];
                ai0 = fmaf(vi.x,h0,ai0); af0 = fmaf(vf.x,h0,af0); ag0 = fmaf(vg.x,h0,ag0); ao0 = fmaf(vo.x,h0,ao0);
                ai0 = fmaf(vi.y,h1,ai0); af0 = fmaf(vf.y,h1,af0); ag0 = fmaf(vg.y,h1,ag0); ao0 = fmaf(vo.y,h1,ao0);
                ai0 = fmaf(vi.z,h2,ai0); af0 = fmaf(vf.z,h2,af0); ag0 = fmaf(vg.z,h2,ag0); ao0 = fmaf(vo.z,h2,ao0);
                ai0 = fmaf(vi.w,h3,ai0); af0 = fmaf(vf.w,h3,af0); ag0 = fmaf(vg.w,h3,ag0); ao0 = fmaf(vo.w,h3,ao0);
            }
            {
                float4 vi = wi[k4+1], vf = wf[k4+1], vg = wg[k4+1], vo = wo[k4+1];
                int k = (k4+1) << 2;
                float h0 = Hh[(k+0)*32 + b], h1 = Hh[(k+1)*32 + b];
                float h2 = Hh[(k+2)*32 + b], h3 = Hh[(k+3)*32 + b];
                ai1 = fmaf(vi.x,h0,ai1); af1 = fmaf(vf.x,h0,af1); ag1 = fmaf(vg.x,h0,ag1); ao1 = fmaf(vo.x,h0,ao1);
                ai1 = fmaf(vi.y,h1,ai1); af1 = fmaf(vf.y,h1,af1); ag1 = fmaf(vg.y,h1,ag1); ao1 = fmaf(vo.y,h1,ao1);
                ai1 = fmaf(vi.z,h2,ai1); af1 = fmaf(vf.z,h2,af1); ag1 = fmaf(vg.z,h2,ag1); ao1 = fmaf(vo.z,h2,ao1);
                ai1 = fmaf(vi.w,h3,ai1); af1 = fmaf(vf.w,h3,af1); ag1 = fmaf(vg.w,h3,ag1); ao1 = fmaf(vo.w,h3,ao1);
            }
        }
        float ai = ai0 + ai1, af = af0 + af1, ag = ag0 + ag1, ao = ao0 + ao1;

        if (q != 0) {
            int o = jl*32 + b;
            Ps[(q-1)*512 + 0*128 + o] = ai;
            Ps[(q-1)*512 + 1*128 + o] = af;
            Ps[(q-1)*512 + 2*128 + o] = ag;
            Ps[(q-1)*512 + 3*128 + o] = ao;
        }
        __syncthreads();
        if (q == 0) {
            int o = jl*32 + b;
            ai += Ps[0*512 + 0*128 + o] + Ps[1*512 + 0*128 + o] + Ps[2*512 + 0*128 + o];
            af += Ps[0*512 + 1*128 + o] + Ps[1*512 + 1*128 + o] + Ps[2*512 + 1*128 + o];
            ag += Ps[0*512 + 2*128 + o] + Ps[1*512 + 2*128 + o] + Ps[2*512 + 2*128 + o];
            ao += Ps[0*512 + 3*128 + o] + Ps[1*512 + 3*128 + o] + Ps[2*512 + 3*128 + o];
            float ig = sigmoidf_(ai), fg = sigmoidf_(af);
            float gg = tanhf(ag),    og = sigmoidf_(ao);
            float c_new = fmaf(fg, creg, ig * gg);
            float h_new = og * tanhf(c_new);
            creg = c_new;
            hbuf[((t+1)&1) * HH*BB + jg*32 + b] = h_new;
            ys[(size_t)m * HH + jg] = h_new;
            if (t == TT-1) cbuf[jg*32 + b] = creg;
            __threadfence();
        }
        __syncthreads();
        if (tid == 0) {
            atomicAdd(&bar[t], 1);
            while (vbar[t] < (int)gridDim.x) { }
            __threadfence();
        }
        __syncthreads();
    }
}

// ---- ctx: exact softmax shortcut = masked mean over S ----
__global__ void ctx_kernel(const float* __restrict__ enc, const int* __restrict__ src_mask,
                           float* __restrict__ ctx) {
    int b = blockIdx.x, h = threadIdx.x;
    float s_un = 0.f, s_all = 0.f; int cnt = 0;
    #pragma unroll 4
    for (int s = 0; s < SS; s++) {
        float v = enc[((size_t)s * BB + b) * HH + h];
        s_all += v;
        if (src_mask[s * BB + b] == 0) { s_un += v; cnt++; }
    }
    ctx[b * HH + h] = (cnt > 0) ? (s_un / (float)cnt) : (s_all / (float)SS);
}

// ---- fp16 single-pass logits GEMM: out[2048,32000] = Acat @ W2cat^T --------
// err ~2e-4 (norm): per-side fp16 rounding 2^-12 rms. 2 planes, double buffer.
#define CHUNKS 16
#define BUFSTR2 (2*PLANE)
#define GSMEM_LG (2*BUFSTR2)     // 64 KB

__global__ __launch_bounds__(256, 1)
void gemm_logits_mma(const __half* __restrict__ Ah, const __half* __restrict__ Bh,
                     float* __restrict__ out) {
    uint32_t sb = s2u(dynsmem);
    int tid = threadIdx.x, wid = tid >> 5, lane = tid & 31;
    int bm = blockIdx.x * 128, bn = blockIdx.y * 128;
    int wm = (wid & 3) * 32, wn = (wid >> 2) * 64;

    float acc[2][8][4];
    #pragma unroll
    for (int mt = 0; mt < 2; mt++)
        #pragma unroll
        for (int nt = 0; nt < 8; nt++)
            #pragma unroll
            for (int q = 0; q < 4; q++) acc[mt][nt][q] = 0.f;

    const __half* gsrc[2] = {Ah, Bh};
    auto fill = [&](int c, int buf) {
        uint32_t base = sb + buf * BUFSTR2;
        #pragma unroll
        for (int it = 0; it < 8; it++) {
            int i = tid + it * 256;
            int p = i >> 10, j = i & 1023;
            int r = j >> 3, seg = j & 7;
            int grow = (p == 0) ? (bm + r) : (bn + r);
            const __half* g = gsrc[p] + ((size_t)grow << 10) + (c << 6) + (seg << 3);
            cp16(base + p * PLANE + SWZ((uint32_t)(r * 128 + seg * 16)), g);
        }
        CP_COMMIT();
    };

    fill(0, 0);
    for (int c = 0; c < CHUNKS; c++) {
        int buf = c & 1;
        if (c + 1 < CHUNKS) { fill(c + 1, buf ^ 1); CP_WAIT1(); }
        else                { CP_WAIT0(); }
        __syncthreads();
        uint32_t base = sb + buf * BUFSTR2;
        #pragma unroll
        for (int kk = 0; kk < 4; kk++) {
            uint32_t af[2][4];
            #pragma unroll
            for (int mt = 0; mt < 2; mt++) {
                int r = wm + mt * 16 + (lane & 15);
                uint32_t off = SWZ((uint32_t)(r * 128 + kk * 32 + (lane >> 4) * 16));
                ldsm4(af[mt], base + 0 * PLANE + off);
            }
            uint32_t bf[4][4];
            #pragma unroll
            for (int np = 0; np < 4; np++) {
                int nrow = wn + np * 16 + (lane & 7) + ((lane >> 4) << 3);
                uint32_t off = SWZ((uint32_t)(nrow * 128 + kk * 32 + ((lane >> 3) & 1) * 16));
                ldsm4(bf[np], base + 1 * PLANE + off);
            }
            #pragma unroll
            for (int mt = 0; mt < 2; mt++)
                #pragma unroll
                for (int nt = 0; nt < 8; nt++)
                    mma16816_fp(acc[mt][nt], af[mt], &bf[nt >> 1][(nt & 1) * 2]);
        }
        __syncthreads();
    }
    #pragma unroll
    for (int mt = 0; mt < 2; mt++) {
        int r0 = bm + wm + mt * 16 + (lane >> 2);
        #pragma unroll
        for (int nt = 0; nt < 8; nt++) {
            int cidx = bn + wn + nt * 8 + (lane & 3) * 2;
            *reinterpret_cast<float2*>(out + (size_t)r0 * VV + cidx) =
                make_float2(acc[mt][nt][0], acc[mt][nt][1]);
            *reinterpret_cast<float2*>(out + (size_t)(r0 + 8) * VV + cidx) =
                make_float2(acc[mt][nt][2], acc[mt][nt][3]);
        }
    }
}

// ---- tail: hs / cs ----
__global__ void tail_kernel(const float* __restrict__ ys0, const float* __restrict__ ys1,
                            const float* __restrict__ c0, const float* __restrict__ c1,
                            float* __restrict__ out) {
    int idx = blockIdx.x * blockDim.x + threadIdx.x;
    if (idx >= 4*HH*BB) return;
    int seg = idx >> 14, i = idx & 16383;
    int b = i >> 9, j = i & 511;
    float v;
    if      (seg == 0) v = ys0[((size_t)(TT-1)*BB + b) * HH + j];
    else if (seg == 1) v = ys1[((size_t)(TT-1)*BB + b) * HH + j];
    else if (seg == 2) v = c0[j*32 + b];
    else               v = c1[j*32 + b];
    out[(size_t)MROWS * VV + idx] = v;
}

// ---- launch ----
extern "C" void kernel_launch(void* const* d_in, const int* in_sizes, int n_in,
                              void* d_out, int out_size) {
    (void)in_sizes; (void)n_in; (void)out_size;
    const int*   tgt     = (const int*)  d_in[0];
    const float* hidden  = (const float*)d_in[1];
    const float* cell    = (const float*)d_in[2];
    const float* enc     = (const float*)d_in[3];
    const int*   srcmask = (const int*)  d_in[4];
    const float* emb     = (const float*)d_in[5];
    const float* Wih0    = (const float*)d_in[6];
    const float* Whh0    = (const float*)d_in[7];
    const float* bih0    = (const float*)d_in[8];
    const float* bhh0    = (const float*)d_in[9];
    const float* Wih1    = (const float*)d_in[10];
    const float* Whh1    = (const float*)d_in[11];
    const float* bih1    = (const float*)d_in[12];
    const float* bhh1    = (const float*)d_in[13];
    // d_in[14] = W1: provably irrelevant (softmax shortcut)
    const float* W2      = (const float*)d_in[15];
    float* out = (float*)d_out;

    float *p_x, *p_xw, *p_ys0, *p_ys1, *p_h0, *p_h1, *p_c0, *p_c1, *p_ctx;
    __half *p_Ah, *p_Wh;
    __nv_bfloat16 *p_xh, *p_xl, *p_wih_h, *p_wih_l;
    int *p_bar;
    cudaGetSymbolAddress((void**)&p_x,     g_x);
    cudaGetSymbolAddress((void**)&p_xw,    g_xw);
    cudaGetSymbolAddress((void**)&p_ys0,   g_ys0);
    cudaGetSymbolAddress((void**)&p_ys1,   g_ys1);
    cudaGetSymbolAddress((void**)&p_h0,    g_h0);
    cudaGetSymbolAddress((void**)&p_h1,    g_h1);
    cudaGetSymbolAddress((void**)&p_c0,    g_c0);
    cudaGetSymbolAddress((void**)&p_c1,    g_c1);
    cudaGetSymbolAddress((void**)&p_ctx,   g_ctx);
    cudaGetSymbolAddress((void**)&p_Ah,    g_Ah);
    cudaGetSymbolAddress((void**)&p_Wh,    g_Wh);
    cudaGetSymbolAddress((void**)&p_xh,    g_xh);
    cudaGetSymbolAddress((void**)&p_xl,    g_xl);
    cudaGetSymbolAddress((void**)&p_wih_h, g_wih_h);
    cudaGetSymbolAddress((void**)&p_wih_l, g_wih_l);
    cudaGetSymbolAddress((void**)&p_bar,   g_bar);

    const int PERSIST_SMEM = (4*4*HH + HH*BB + 1536) * sizeof(float);  // ~104 KB
    cudaFuncSetAttribute(lstm_persist, cudaFuncAttributeMaxDynamicSharedMemorySize, PERSIST_SMEM);
    cudaFuncSetAttribute(gemm_logits_mma, cudaFuncAttributeMaxDynamicSharedMemorySize, GSMEM_LG);
    cudaFuncSetAttribute(gemm_xw_mma, cudaFuncAttributeMaxDynamicSharedMemorySize, GSMEM_XW);

    init_state<<<64, 256>>>(hidden, cell, p_h0, p_h1, p_c0, p_c1, p_bar);
    gather_emb<<<MROWS, 128>>>(tgt, emb, p_x);
    conv_w_h<<<(int)(((size_t)VV*KTOT)/8/256), 256>>>(W2, p_Wh);

    // layer 0
    conv_flat<<<512, 256>>>(p_x, p_xh, p_xl);
    conv_flat<<<512, 256>>>(Wih0, p_wih_h, p_wih_l);
    gemm_xw_mma<<<dim3(16, 16), 256, GSMEM_XW>>>(p_xh, p_xl, p_wih_h, p_wih_l, p_xw, bih0, bhh0);
    lstm_persist<<<128, 512, PERSIST_SMEM>>>(p_xw, Whh0, p_h0, p_c0, p_ys0, p_bar);

    // layer 1
    conv_flat<<<512, 256>>>(p_ys0, p_xh, p_xl);
    conv_flat<<<512, 256>>>(Wih1, p_wih_h, p_wih_l);
    gemm_xw_mma<<<dim3(16, 16), 256, GSMEM_XW>>>(p_xh, p_xl, p_wih_h, p_wih_l, p_xw, bih1, bhh1);
    lstm_persist<<<128, 512, PERSIST_SMEM>>>(p_xw, Whh1, p_h1, p_c1, p_ys1, p_bar + TT);

    ctx_kernel<<<BB, HH>>>(enc, srcmask, p_ctx);
    conv_a_h<<<MROWS, 128>>>(p_ys1, p_ctx, p_Ah);
    gemm_logits_mma<<<dim3(MROWS/128, VV/128), 256, GSMEM_LG>>>(p_Ah, p_Wh, out);

    tail_kernel<<<64, 1024>>>(p_ys0, p_ys1, p_c0, p_c1, out);
}